// round 14
// baseline (speedup 1.0000x reference)
#include <cuda_runtime.h>
#include <cuda_bf16.h>
#include <math.h>
#include <stdint.h>

#define BB 2
#define SS 2048
#define EE 128
#define HH 16
#define DD 128
#define DHH 512
#define MM (BB*SS)     // 4096 rows
#define HD (HH*DD)     // 2048

// ---------------- scratch (static __device__, no allocation) ----------------
__device__ float g_x2[MM*EE];
__device__ float g_part[4*MM*EE];
__device__ __nv_bfloat16 g_h1h[MM*EE],  g_h1l[MM*EE];
__device__ __nv_bfloat16 g_h2h[MM*EE],  g_h2l[MM*EE];
__device__ __nv_bfloat16 g_th [MM*DHH], g_tl [MM*DHH];
__device__ __nv_bfloat16 g_aoh[MM*HD],  g_aol[MM*HD];
__device__ __nv_bfloat16 g_qhi[MM*HD],  g_qlo[MM*HD];
__device__ __nv_bfloat16 g_khi[MM*HD],  g_klo[MM*HD];
__device__ __nv_bfloat16 g_vhi[MM*HD],  g_vlo[MM*HD];
__device__ __nv_bfloat16 g_wqh[EE*HD],  g_wql[EE*HD];
__device__ __nv_bfloat16 g_wkh[EE*HD],  g_wkl[EE*HD];
__device__ __nv_bfloat16 g_wvh[EE*HD],  g_wvl[EE*HD];
__device__ __nv_bfloat16 g_woh[HD*EE],  g_wol[HD*EE];
__device__ __nv_bfloat16 g_f1h[EE*DHH], g_f1l[EE*DHH];
__device__ __nv_bfloat16 g_f2h[DHH*EE], g_f2l[DHH*EE];

// ======================= warp MMA helpers (baseline PTX) =====================
__device__ __forceinline__ uint32_t smem_u32(const void* p) {
    uint32_t a;
    asm("{ .reg .u64 t; cvta.to.shared.u64 t, %1; cvt.u32.u64 %0, t; }"
        : "=r"(a) : "l"(p));
    return a;
}
__device__ __forceinline__ void mma16816(float* c, const uint32_t* a, const uint32_t* b) {
    asm volatile(
        "mma.sync.aligned.m16n8k16.row.col.f32.bf16.bf16.f32 "
        "{%0,%1,%2,%3}, {%4,%5,%6,%7}, {%8,%9}, {%0,%1,%2,%3};"
        : "+f"(c[0]), "+f"(c[1]), "+f"(c[2]), "+f"(c[3])
        : "r"(a[0]), "r"(a[1]), "r"(a[2]), "r"(a[3]), "r"(b[0]), "r"(b[1]));
}
__device__ __forceinline__ void ldsm_x4(uint32_t* r, uint32_t addr) {
    asm volatile("ldmatrix.sync.aligned.m8n8.x4.shared.b16 {%0,%1,%2,%3}, [%4];"
        : "=r"(r[0]), "=r"(r[1]), "=r"(r[2]), "=r"(r[3]) : "r"(addr));
}
__device__ __forceinline__ void ldsm_x4_t(uint32_t* r, uint32_t addr) {
    asm volatile("ldmatrix.sync.aligned.m8n8.x4.trans.shared.b16 {%0,%1,%2,%3}, [%4];"
        : "=r"(r[0]), "=r"(r[1]), "=r"(r[2]), "=r"(r[3]) : "r"(addr));
}
__device__ __forceinline__ uint32_t pack_bf2(float a, float b) {
    __nv_bfloat162 h = __halves2bfloat162(__float2bfloat16(a), __float2bfloat16(b));
    return *(uint32_t*)&h;
}
__device__ __forceinline__ void cp16(uint32_t smem_addr, const void* gptr) {
    asm volatile("cp.async.cg.shared.global [%0], [%1], 16;"
        :: "r"(smem_addr), "l"(gptr) : "memory");
}
#define CP_COMMIT() asm volatile("cp.async.commit_group;" ::: "memory")
#define CP_WAIT(n)  asm volatile("cp.async.wait_group %0;" :: "n"(n) : "memory")

// 256B-row swizzle (B tiles, FA tiles); 128B-row swizzle (A tiles)
__device__ __forceinline__ uint32_t boff(int r, int cbyte) {
    return (uint32_t)(r * 256 + (cbyte ^ ((r & 7) << 4)));
}
__device__ __forceinline__ uint32_t aoff(int r, int cbyte) {
    return (uint32_t)(r * 128 + (cbyte ^ ((r & 7) << 4)));
}

// ---------------- fp32 -> bf16 hi/lo split: all six weights in ONE launch ----
__global__ void split6(const float* __restrict__ a0, const float* __restrict__ a1,
                       const float* __restrict__ a2, const float* __restrict__ a3,
                       const float* __restrict__ a4, const float* __restrict__ a5,
                       __nv_bfloat16* h0, __nv_bfloat16* l0,
                       __nv_bfloat16* h1, __nv_bfloat16* l1,
                       __nv_bfloat16* h2, __nv_bfloat16* l2,
                       __nv_bfloat16* h3, __nv_bfloat16* l3,
                       __nv_bfloat16* h4, __nv_bfloat16* l4,
                       __nv_bfloat16* h5, __nv_bfloat16* l5) {
    const float* ws[6] = {a0, a1, a2, a3, a4, a5};
    __nv_bfloat16* hs[6] = {h0, h1, h2, h3, h4, h5};
    __nv_bfloat16* ls[6] = {l0, l1, l2, l3, l4, l5};
    int b = blockIdx.x, wi, off;
    if (b < 1024) { wi = b >> 8;       off = (b & 255) * 1024; }
    else          { b -= 1024; wi = 4 + (b >> 6); off = (b & 63) * 1024; }
    int i = off + threadIdx.x * 4;
    float4 v = *(const float4*)(ws[wi] + i);
    __nv_bfloat16 b0 = __float2bfloat16(v.x), b1 = __float2bfloat16(v.y);
    __nv_bfloat16 b2 = __float2bfloat16(v.z), b3 = __float2bfloat16(v.w);
    __nv_bfloat162 hh01 = __halves2bfloat162(b0, b1), hh23 = __halves2bfloat162(b2, b3);
    *(uint2*)(hs[wi] + i) = make_uint2(*(uint32_t*)&hh01, *(uint32_t*)&hh23);
    uint32_t l01 = pack_bf2(v.x - __bfloat162float(b0), v.y - __bfloat162float(b1));
    uint32_t l23 = pack_bf2(v.z - __bfloat162float(b2), v.w - __bfloat162float(b3));
    *(uint2*)(ls[wi] + i) = make_uint2(l01, l23);
}

// ---------------- split-K reduce: out = resid (+bias) + sum partials --------
template<int NS, bool BIAS>
__global__ void reduce_k(const float* __restrict__ part, const float* __restrict__ resid,
                         const float* __restrict__ bias, float* __restrict__ out) {
    int i = (blockIdx.x * 256 + threadIdx.x) * 4;
    float4 acc = *(const float4*)(resid + i);
    if (BIAS) {
        float4 bv = *(const float4*)(bias + (i & (EE - 1)));
        acc.x += bv.x; acc.y += bv.y; acc.z += bv.z; acc.w += bv.w;
    }
    #pragma unroll
    for (int z = 0; z < NS; z++) {
        float4 p = *(const float4*)(part + (size_t)z * (MM * EE) + i);
        acc.x += p.x; acc.y += p.y; acc.z += p.z; acc.w += p.w;
    }
    *(float4*)(out + i) = acc;
}

// ---------------- LayerNorm: one warp per row, bf16 hi/lo out ---------------
__global__ void ln_kernel(const float* __restrict__ x, const float* __restrict__ g,
                          const float* __restrict__ b,
                          __nv_bfloat16* __restrict__ ohi, __nv_bfloat16* __restrict__ olo) {
    int warp = threadIdx.x >> 5, lane = threadIdx.x & 31;
    int row = blockIdx.x * 8 + warp;
    float4 v = ((const float4*)(x + (size_t)row * EE))[lane];
    float s = v.x + v.y + v.z + v.w;
    #pragma unroll
    for (int o = 16; o; o >>= 1) s += __shfl_xor_sync(0xffffffffu, s, o);
    float mu = s * (1.0f / EE);
    float d0 = v.x - mu, d1 = v.y - mu, d2 = v.z - mu, d3 = v.w - mu;
    float q = d0*d0 + d1*d1 + d2*d2 + d3*d3;
    #pragma unroll
    for (int o = 16; o; o >>= 1) q += __shfl_xor_sync(0xffffffffu, q, o);
    float inv = rsqrtf(q * (1.0f / EE) + 1e-5f);
    float4 gg = ((const float4*)g)[lane];
    float4 bb = ((const float4*)b)[lane];
    float r0 = d0 * inv * gg.x + bb.x;
    float r1 = d1 * inv * gg.y + bb.y;
    float r2 = d2 * inv * gg.z + bb.z;
    float r3 = d3 * inv * gg.w + bb.w;
    __nv_bfloat16 h0 = __float2bfloat16(r0), h1 = __float2bfloat16(r1);
    __nv_bfloat16 h2 = __float2bfloat16(r2), h3 = __float2bfloat16(r3);
    __nv_bfloat162 hh01 = __halves2bfloat162(h0, h1), hh23 = __halves2bfloat162(h2, h3);
    size_t base = (size_t)row * EE + lane * 4;
    *(uint2*)(ohi + base) = make_uint2(*(uint32_t*)&hh01, *(uint32_t*)&hh23);
    uint32_t l01 = pack_bf2(r0 - __bfloat162float(h0), r1 - __bfloat162float(h1));
    uint32_t l23 = pack_bf2(r2 - __bfloat162float(h2), r3 - __bfloat162float(h3));
    *(uint2*)(olo + base) = make_uint2(l01, l23);
}

// =============== shared smem layout for projection GEMMs (2 stages) =========
#define MM3_AHI 0u
#define MM3_ALO 16384u
#define MM3_BHI 32768u
#define MM3_BLO 49152u
#define MM3_STAGE 65536u
#define MM3_SMEM 131072

// =============== fused QKV projection (pipelined, bf16x3) ===================
__global__ __launch_bounds__(256, 1)
void qkv_mm(float qscale)
{
    extern __shared__ char sm[];
    uint32_t sb = smem_u32(sm);
    const int tid = threadIdx.x;
    const int w = tid >> 5, ln = tid & 31;
    const int tig = ln & 3, gid = ln >> 2;
    const int mi = blockIdx.x >> 4;
    const int n0 = (blockIdx.x & 15) * 128;
    const int m0 = blockIdx.y * 128;
    const __nv_bfloat16* Bh_ = (mi == 0) ? g_wqh : (mi == 1) ? g_wkh : g_wvh;
    const __nv_bfloat16* Bl_ = (mi == 0) ? g_wql : (mi == 1) ? g_wkl : g_wvl;
    __nv_bfloat16* Oh_ = (mi == 0) ? g_qhi : (mi == 1) ? g_khi : g_vhi;
    __nv_bfloat16* Ol_ = (mi == 0) ? g_qlo : (mi == 1) ? g_klo : g_vlo;
    const float scale = (mi == 0) ? qscale : 1.0f;

    float C[16][4];
    #pragma unroll
    for (int j = 0; j < 16; j++)
        #pragma unroll
        for (int e = 0; e < 4; e++) C[j][e] = 0.f;

    const int arow = 16 * w + ((ln >> 3) & 1) * 8 + (ln & 7);
    const int akb  = (ln >> 4) * 16;
    const int brow = ((ln >> 3) & 1) * 8 + (ln & 7);
    const int bcb  = (ln >> 4) << 4;

    // prologue: prefetch k-iter 0 into stage 0
    for (int f = tid; f < 1024; f += 256) {
        int r = f >> 3, seg = f & 7;
        size_t g = (size_t)(m0 + r) * EE + seg * 8;
        uint32_t so = aoff(r, seg * 16);
        cp16(sb + MM3_AHI + so, g_h1h + g);
        cp16(sb + MM3_ALO + so, g_h1l + g);
    }
    for (int f = tid; f < 1024; f += 256) {
        int r = f >> 4, seg = f & 15;
        size_t g = (size_t)r * HD + n0 + seg * 8;
        uint32_t so = boff(r, seg * 16);
        cp16(sb + MM3_BHI + so, Bh_ + g);
        cp16(sb + MM3_BLO + so, Bl_ + g);
    }
    CP_COMMIT();

    #pragma unroll
    for (int it = 0; it < 2; it++) {
        uint32_t st = (uint32_t)(it & 1) * MM3_STAGE;
        __syncthreads();
        if (it == 0) {
            for (int f = tid; f < 1024; f += 256) {
                int r = f >> 3, seg = f & 7;
                size_t g = (size_t)(m0 + r) * EE + 64 + seg * 8;
                uint32_t so = aoff(r, seg * 16);
                cp16(sb + MM3_STAGE + MM3_AHI + so, g_h1h + g);
                cp16(sb + MM3_STAGE + MM3_ALO + so, g_h1l + g);
            }
            for (int f = tid; f < 1024; f += 256) {
                int r = f >> 4, seg = f & 15;
                size_t g = (size_t)(64 + r) * HD + n0 + seg * 8;
                uint32_t so = boff(r, seg * 16);
                cp16(sb + MM3_STAGE + MM3_BHI + so, Bh_ + g);
                cp16(sb + MM3_STAGE + MM3_BLO + so, Bl_ + g);
            }
            CP_COMMIT();
            CP_WAIT(1);
        } else {
            CP_WAIT(0);
        }
        __syncthreads();

        uint32_t Ah[4][4], Al[4][4];
        #pragma unroll
        for (int kk = 0; kk < 4; kk++) {
            uint32_t off = aoff(arow, kk * 32 + akb);
            ldsm_x4(Ah[kk], sb + st + MM3_AHI + off);
            ldsm_x4(Al[kk], sb + st + MM3_ALO + off);
        }
        #pragma unroll
        for (int jp = 0; jp < 8; jp++) {
            int ncb = 32 * jp;
            #pragma unroll
            for (int kk = 0; kk < 4; kk++) {
                uint32_t off = boff(16 * kk + brow, ncb + bcb);
                uint32_t Bh[4], Bl[4];
                ldsm_x4_t(Bh, sb + st + MM3_BHI + off);
                mma16816(C[2*jp],   Ah[kk], Bh);
                mma16816(C[2*jp+1], Ah[kk], Bh + 2);
                mma16816(C[2*jp],   Al[kk], Bh);
                mma16816(C[2*jp+1], Al[kk], Bh + 2);
                ldsm_x4_t(Bl, sb + st + MM3_BLO + off);
                mma16816(C[2*jp],   Ah[kk], Bl);
                mma16816(C[2*jp+1], Ah[kk], Bl + 2);
            }
        }
    }

    // epilogue: scale, RoPE (Q/K), bf16 hi/lo split to (B,H,S,D)
    const int r0 = m0 + 16 * w + gid;
    const int r1 = r0 + 8;
    int b_ = r0 >> 11, s0 = r0 & 2047, s1 = r1 & 2047;
    #pragma unroll
    for (int j = 0; j < 16; j++) {
        int colg = n0 + 8 * j + 2 * tig;
        int h = colg >> 7, d = colg & 127;
        float o00 = C[j][0] * scale, o01 = C[j][1] * scale;
        float o10 = C[j][2] * scale, o11 = C[j][3] * scale;
        if (mi < 2) {
            int t2 = d >> 1;
            float f = expf((float)t2 * -0.14391157f);
            float si0, co0, si1, co1;
            sincosf((float)s0 * f, &si0, &co0);
            sincosf((float)s1 * f, &si1, &co1);
            float a = o00 * co0 - o01 * si0, b2 = o00 * si0 + o01 * co0;
            o00 = a; o01 = b2;
            a = o10 * co1 - o11 * si1; b2 = o10 * si1 + o11 * co1;
            o10 = a; o11 = b2;
        }
        size_t oi0 = (((size_t)(b_ * HH + h) * SS + s0) * DD + d);
        size_t oi1 = (((size_t)(b_ * HH + h) * SS + s1) * DD + d);
        __nv_bfloat16 h00 = __float2bfloat16(o00), h01 = __float2bfloat16(o01);
        __nv_bfloat16 h10 = __float2bfloat16(o10), h11 = __float2bfloat16(o11);
        __nv_bfloat162 p0 = __halves2bfloat162(h00, h01);
        __nv_bfloat162 p1 = __halves2bfloat162(h10, h11);
        *(uint32_t*)(Oh_ + oi0) = *(uint32_t*)&p0;
        *(uint32_t*)(Oh_ + oi1) = *(uint32_t*)&p1;
        *(uint32_t*)(Ol_ + oi0) = pack_bf2(o00 - __bfloat162float(h00), o01 - __bfloat162float(h01));
        *(uint32_t*)(Ol_ + oi1) = pack_bf2(o10 - __bfloat162float(h10), o11 - __bfloat162float(h11));
    }
}

// =============== bf16x3 tensor-core GEMM (pipelined) ========================
// MODE 4: gelu(acc + bias) -> bf16 hi/lo               (fc1)
// MODE 6: split-K partial: fp32 to out + blockIdx.x*M*N, k in [bx*kspl, +kspl)
template<int MODE, bool AG, bool HALFM>
__global__ __launch_bounds__(256)
void mm3(const __nv_bfloat16* __restrict__ Ahi, const __nv_bfloat16* __restrict__ Alo,
         const __nv_bfloat16* __restrict__ Bhi, const __nv_bfloat16* __restrict__ Blo,
         const float* __restrict__ bias, const float* __restrict__ resid,
         float* __restrict__ out,
         __nv_bfloat16* __restrict__ ohi, __nv_bfloat16* __restrict__ olo,
         int M, int N, int K, int kspl, float qscale)
{
    extern __shared__ char sm[];
    uint32_t sb = smem_u32(sm);
    constexpr int MT = HALFM ? 64 : 128;
    constexpr int NJ = HALFM ? 8 : 16;
    const int tid = threadIdx.x;
    const int w = tid >> 5, ln = tid & 31;
    const int tig = ln & 3, gid = ln >> 2;
    const int wr = HALFM ? (w & 3) : w;
    const int wc = HALFM ? (w >> 2) * 64 : 0;
    const int m0 = blockIdx.y * MT;
    const int n0 = (MODE == 6) ? 0 : blockIdx.x * 128;
    const int kb = (MODE == 6) ? blockIdx.x * kspl : 0;
    const int ke = (MODE == 6) ? kb + kspl : K;
    const int niter = (ke - kb) >> 6;

    float C[NJ][4];
    #pragma unroll
    for (int j = 0; j < NJ; j++)
        #pragma unroll
        for (int e = 0; e < 4; e++) C[j][e] = 0.f;

    const int arow = 16 * wr + ((ln >> 3) & 1) * 8 + (ln & 7);
    const int akb  = (ln >> 4) * 16;
    const int brow = ((ln >> 3) & 1) * 8 + (ln & 7);
    const int bcb  = (ln >> 4) << 4;

    // prologue: prefetch iter 0
    {
        int k0 = kb;
        for (int f = tid; f < MT * 8; f += 256) {
            int r = f >> 3, seg = f & 7;
            size_t g;
            if (!AG) {
                g = (size_t)(m0 + r) * K + k0 + seg * 8;
            } else {
                int rr = m0 + r;
                int b_ = rr >> 11, s_ = rr & 2047;
                int kk = k0 + seg * 8;
                g = ((size_t)(b_ * HH + (kk >> 7)) * SS + s_) * DD + (kk & 127);
            }
            uint32_t so = aoff(r, seg * 16);
            cp16(sb + MM3_AHI + so, Ahi + g);
            cp16(sb + MM3_ALO + so, Alo + g);
        }
        for (int f = tid; f < 1024; f += 256) {
            int r = f >> 4, seg = f & 15;
            size_t g = (size_t)(k0 + r) * N + n0 + seg * 8;
            uint32_t so = boff(r, seg * 16);
            cp16(sb + MM3_BHI + so, Bhi + g);
            cp16(sb + MM3_BLO + so, Blo + g);
        }
        CP_COMMIT();
    }

    for (int it = 0; it < niter; it++) {
        uint32_t st = (uint32_t)(it & 1) * MM3_STAGE;
        __syncthreads();
        if (it + 1 < niter) {
            int k0 = kb + (it + 1) * 64;
            uint32_t stn = (uint32_t)((it + 1) & 1) * MM3_STAGE;
            for (int f = tid; f < MT * 8; f += 256) {
                int r = f >> 3, seg = f & 7;
                size_t g;
                if (!AG) {
                    g = (size_t)(m0 + r) * K + k0 + seg * 8;
                } else {
                    int rr = m0 + r;
                    int b_ = rr >> 11, s_ = rr & 2047;
                    int kk = k0 + seg * 8;
                    g = ((size_t)(b_ * HH + (kk >> 7)) * SS + s_) * DD + (kk & 127);
                }
                uint32_t so = aoff(r, seg * 16);
                cp16(sb + stn + MM3_AHI + so, Ahi + g);
                cp16(sb + stn + MM3_ALO + so, Alo + g);
            }
            for (int f = tid; f < 1024; f += 256) {
                int r = f >> 4, seg = f & 15;
                size_t g = (size_t)(k0 + r) * N + n0 + seg * 8;
                uint32_t so = boff(r, seg * 16);
                cp16(sb + stn + MM3_BHI + so, Bhi + g);
                cp16(sb + stn + MM3_BLO + so, Blo + g);
            }
            CP_COMMIT();
            CP_WAIT(1);
        } else {
            CP_WAIT(0);
        }
        __syncthreads();

        uint32_t Ah[4][4], Al[4][4];
        #pragma unroll
        for (int kk = 0; kk < 4; kk++) {
            uint32_t off = aoff(arow, kk * 32 + akb);
            ldsm_x4(Ah[kk], sb + st + MM3_AHI + off);
            ldsm_x4(Al[kk], sb + st + MM3_ALO + off);
        }
        #pragma unroll
        for (int jp = 0; jp < NJ / 2; jp++) {
            int ncb = (wc + 16 * jp) * 2;
            #pragma unroll
            for (int kk = 0; kk < 4; kk++) {
                uint32_t off = boff(16 * kk + brow, ncb + bcb);
                uint32_t Bh[4], Bl[4];
                ldsm_x4_t(Bh, sb + st + MM3_BHI + off);
                mma16816(C[2*jp],   Ah[kk], Bh);
                mma16816(C[2*jp+1], Ah[kk], Bh + 2);
                mma16816(C[2*jp],   Al[kk], Bh);
                mma16816(C[2*jp+1], Al[kk], Bh + 2);
                ldsm_x4_t(Bl, sb + st + MM3_BLO + off);
                mma16816(C[2*jp],   Ah[kk], Bl);
                mma16816(C[2*jp+1], Ah[kk], Bl + 2);
            }
        }
    }

    const int r0 = m0 + 16 * wr + gid;
    const int r1 = r0 + 8;
    if (MODE == 6) {
        float* po = out + (size_t)blockIdx.x * M * N;
        #pragma unroll
        for (int j = 0; j < NJ; j++) {
            int colg = wc + 8 * j + 2 * tig;
            size_t i0 = (size_t)r0 * N + colg;
            size_t i1 = (size_t)r1 * N + colg;
            *(float2*)(po + i0) = make_float2(C[j][0], C[j][1]);
            *(float2*)(po + i1) = make_float2(C[j][2], C[j][3]);
        }
    } else if (MODE == 4) {
        #pragma unroll
        for (int j = 0; j < NJ; j++) {
            int colg = n0 + wc + 8 * j + 2 * tig;
            size_t i0 = (size_t)r0 * N + colg;
            size_t i1 = (size_t)r1 * N + colg;
            float v00 = C[j][0], v01 = C[j][1], v10 = C[j][2], v11 = C[j][3];
            float b0 = bias[colg], b1 = bias[colg + 1];
            v00 += b0; v01 += b1; v10 += b0; v11 += b1;
            v00 = 0.5f * v00 * (1.0f + erff(v00 * 0.70710678f));
            v01 = 0.5f * v01 * (1.0f + erff(v01 * 0.70710678f));
            v10 = 0.5f * v10 * (1.0f + erff(v10 * 0.70710678f));
            v11 = 0.5f * v11 * (1.0f + erff(v11 * 0.70710678f));
            __nv_bfloat16 h00 = __float2bfloat16(v00), h01 = __float2bfloat16(v01);
            __nv_bfloat16 h10 = __float2bfloat16(v10), h11 = __float2bfloat16(v11);
            __nv_bfloat162 p0 = __halves2bfloat162(h00, h01);
            __nv_bfloat162 p1 = __halves2bfloat162(h10, h11);
            *(uint32_t*)(ohi + i0) = *(uint32_t*)&p0;
            *(uint32_t*)(ohi + i1) = *(uint32_t*)&p1;
            *(uint32_t*)(olo + i0) = pack_bf2(v00 - __bfloat162float(h00), v01 - __bfloat162float(h01));
            *(uint32_t*)(olo + i1) = pack_bf2(v10 - __bfloat162float(h10), v11 - __bfloat162float(h11));
        }
    }
}

// ============== mma.sync flash attention (bf16x3, 2 CTAs/SM) ================
// CTA: 128 threads, 64 query rows. Grid 1024 (globally-descending work).
// Smem/CTA = 112KB: K [0,32K), V double [32K,96K), Qlo resident [96K,112K).
// Ql fragments re-loaded from smem per kk (4-reg transient) to relieve the
// 255-reg ceiling (spill removal); accumulation order unchanged.
#define FA_KHI 0u
#define FA_KLO 16384u
#define FA_V0  32768u
#define FA_VST 32768u
#define FA_QLO 98304u
#define FA_SMEM 114688

__device__ __forceinline__ uint32_t fa_off(int r, int cbyte) {
    return (uint32_t)(r * 256 + (cbyte ^ ((r & 7) << 4)));
}

__global__ __launch_bounds__(128, 2)
void fa_mma(const __nv_bfloat16* __restrict__ qhi, const __nv_bfloat16* __restrict__ qlo,
            const __nv_bfloat16* __restrict__ khi, const __nv_bfloat16* __restrict__ klo,
            const __nv_bfloat16* __restrict__ vhi, const __nv_bfloat16* __restrict__ vlo,
            __nv_bfloat16* __restrict__ Ohi, __nv_bfloat16* __restrict__ Olo)
{
    extern __shared__ char sm[];
    uint32_t sb = smem_u32(sm);
    const int tid = threadIdx.x;
    const int w = tid >> 5, ln = tid & 31;
    const int tig = ln & 3, gid = ln >> 2;
    const int bid = blockIdx.x;
    const int m0 = (31 - (bid >> 5)) * 64;    // globally descending work
    const int bh = bid & 31;
    const size_t base = (size_t)bh * SS * DD;

    // ---- stage Q: hi via K region (transient), lo into resident FA_QLO ----
    for (int f = tid; f < 1024; f += 128) {
        int r = f >> 4, c16 = f & 15;
        size_t g = base + (size_t)(m0 + r) * DD + c16 * 8;
        uint32_t so = fa_off(r, c16 * 16);
        *(uint4*)(sm + FA_KHI + so) = *(const uint4*)(qhi + g);
        *(uint4*)(sm + FA_QLO + so) = *(const uint4*)(qlo + g);
    }
    __syncthreads();
    const int qrow = 16 * w + ((ln >> 3) & 1) * 8 + (ln & 7);
    const int qkb  = (ln >> 4) * 16;
    uint32_t Qh[8][4];
    #pragma unroll
    for (int kk = 0; kk < 8; kk++)
        ldsm_x4(Qh[kk], sb + FA_KHI + fa_off(qrow, kk * 32 + qkb));
    __syncthreads();

    float Oa[16][4];
    #pragma unroll
    for (int j = 0; j < 16; j++)
        #pragma unroll
        for (int e = 0; e < 4; e++) Oa[j][e] = 0.f;
    float m0r = -1e30f, m1r = -1e30f, l0r = 0.f, l1r = 0.f;

    const int grow0 = m0 + 16 * w + gid;
    const int grow1 = grow0 + 8;
    const int nk = m0 / 64 + 1;

    // ---- prologue: K(0), V(0) ----
    for (int f = tid; f < 1024; f += 128) {
        int r = f >> 4, c16 = f & 15;
        size_t g = base + (size_t)r * DD + c16 * 8;
        uint32_t so = fa_off(r, c16 * 16);
        cp16(sb + FA_KHI + so, khi + g);
        cp16(sb + FA_KLO + so, klo + g);
        cp16(sb + FA_V0 + so, vhi + g);
        cp16(sb + FA_V0 + 16384 + so, vlo + g);
    }
    CP_COMMIT();

    for (int t = 0; t < nk; t++) {
        int n0 = t * 64;
        uint32_t vb = FA_V0 + (uint32_t)(t & 1) * FA_VST;
        CP_WAIT(0);        // K(t), V(t) resident
        __syncthreads();

        // ---- S = Q K^T (3-term); kk outer, Ql re-loaded per kk ----
        float S[8][4];
        #pragma unroll
        for (int j = 0; j < 8; j++)
            #pragma unroll
            for (int e = 0; e < 4; e++) S[j][e] = 0.f;
        {
            int brow = ((ln >> 4) << 3) + (ln & 7);
            int bkb  = ((ln >> 3) & 1) << 4;
            #pragma unroll
            for (int kk = 0; kk < 8; kk++) {
                uint32_t Qlt[4];
                ldsm_x4(Qlt, sb + FA_QLO + fa_off(qrow, kk * 32 + qkb));
                #pragma unroll
                for (int jp = 0; jp < 4; jp++) {
                    int r_ = 16 * jp + brow;
                    uint32_t off = fa_off(r_, kk * 32 + bkb);
                    uint32_t Bh[4], Bl[4];
                    ldsm_x4(Bh, sb + FA_KHI + off);
                    mma16816(S[2*jp],   Qh[kk], Bh);
                    mma16816(S[2*jp+1], Qh[kk], Bh + 2);
                    mma16816(S[2*jp],   Qlt, Bh);
                    mma16816(S[2*jp+1], Qlt, Bh + 2);
                    ldsm_x4(Bl, sb + FA_KLO + off);
                    mma16816(S[2*jp],   Qh[kk], Bl);
                    mma16816(S[2*jp+1], Qh[kk], Bl + 2);
                }
            }
        }
        __syncthreads();   // all warps done reading K(t)

        // ---- prefetch K(t+1) and V(t+1) (overlaps softmax + PV below) ----
        if (t + 1 < nk) {
            int n1 = n0 + 64;
            uint32_t vbn = FA_V0 + (uint32_t)((t + 1) & 1) * FA_VST;
            for (int f = tid; f < 1024; f += 128) {
                int r = f >> 4, c16 = f & 15;
                size_t g = base + (size_t)(n1 + r) * DD + c16 * 8;
                uint32_t so = fa_off(r, c16 * 16);
                cp16(sb + FA_KHI + so, khi + g);
                cp16(sb + FA_KLO + so, klo + g);
                cp16(sb + vbn + so, vhi + g);
                cp16(sb + vbn + 16384 + so, vlo + g);
            }
            CP_COMMIT();
        }

        // ---- causal mask (diagonal tile only) ----
        if (n0 + 63 > m0 + 16 * w) {
            #pragma unroll
            for (int j = 0; j < 8; j++) {
                int c = n0 + 8 * j + 2 * tig;
                if (c     > grow0) S[j][0] = -1e30f;
                if (c + 1 > grow0) S[j][1] = -1e30f;
                if (c     > grow1) S[j][2] = -1e30f;
                if (c + 1 > grow1) S[j][3] = -1e30f;
            }
        }

        // ---- online softmax ----
        float mx0 = -1e30f, mx1 = -1e30f;
        #pragma unroll
        for (int j = 0; j < 8; j++) {
            mx0 = fmaxf(mx0, fmaxf(S[j][0], S[j][1]));
            mx1 = fmaxf(mx1, fmaxf(S[j][2], S[j][3]));
        }
        mx0 = fmaxf(mx0, __shfl_xor_sync(0xffffffffu, mx0, 1));
        mx0 = fmaxf(mx0, __shfl_xor_sync(0xffffffffu, mx0, 2));
        mx1 = fmaxf(mx1, __shfl_xor_sync(0xffffffffu, mx1, 1));
        mx1 = fmaxf(mx1, __shfl_xor_sync(0xffffffffu, mx1, 2));
        float mn0 = fmaxf(m0r, mx0), mn1 = fmaxf(m1r, mx1);
        bool nochg = (mn0 == m0r) && (mn1 == m1r);
        float a0 = nochg ? 1.f : __expf(m0r - mn0);
        float a1 = nochg ? 1.f : __expf(m1r - mn1);
        m0r = mn0; m1r = mn1;
        l0r *= a0; l1r *= a1;

        uint32_t Phi[4][4], Plo[4][4];
        float ls0 = 0.f, ls1 = 0.f;
        #pragma unroll
        for (int j = 0; j < 8; j++) {
            float p0 = __expf(S[j][0] - mn0);
            float p1 = __expf(S[j][1] - mn0);
            float p2 = __expf(S[j][2] - mn1);
            float p3 = __expf(S[j][3] - mn1);
            ls0 += p0 + p1; ls1 += p2 + p3;
            __nv_bfloat16 h0 = __float2bfloat16(p0);
            __nv_bfloat16 h1 = __float2bfloat16(p1);
            __nv_bfloat16 h2 = __float2bfloat16(p2);
            __nv_bfloat16 h3 = __float2bfloat16(p3);
            int kk = j >> 1, q = (j & 1) * 2;
            __nv_bfloat162 hh01 = __halves2bfloat162(h0, h1);
            __nv_bfloat162 hh23 = __halves2bfloat162(h2, h3);
            Phi[kk][q]     = *(uint32_t*)&hh01;
            Phi[kk][q + 1] = *(uint32_t*)&hh23;
            Plo[kk][q]     = pack_bf2(p0 - __bfloat162float(h0), p1 - __bfloat162float(h1));
            Plo[kk][q + 1] = pack_bf2(p2 - __bfloat162float(h2), p3 - __bfloat162float(h3));
        }
        l0r += ls0; l1r += ls1;

        if (!__all_sync(0xffffffffu, nochg)) {
            #pragma unroll
            for (int j = 0; j < 16; j++) {
                Oa[j][0] *= a0; Oa[j][1] *= a0;
                Oa[j][2] *= a1; Oa[j][3] *= a1;
            }
        }

        // ---- O += P V (3-term) ----
        {
            int vrow = ((ln >> 3) & 1) * 8 + (ln & 7);
            int vcb  = (ln >> 4) << 4;
            #pragma unroll
            for (int jp = 0; jp < 8; jp++) {
                #pragma unroll
                for (int kk = 0; kk < 4; kk++) {
                    int r_ = 16 * kk + vrow;
                    uint32_t off = fa_off(r_, 32 * jp + vcb);
                    uint32_t Bh[4], Bl[4];
                    ldsm_x4_t(Bh, sb + vb + off);
                    mma16816(Oa[2*jp],   Phi[kk], Bh);
                    mma16816(Oa[2*jp+1], Phi[kk], Bh + 2);
                    mma16816(Oa[2*jp],   Plo[kk], Bh);
                    mma16816(Oa[2*jp+1], Plo[kk], Bh + 2);
                    ldsm_x4_t(Bl, sb + vb + 16384 + off);
                    mma16816(Oa[2*jp],   Phi[kk], Bl);
                    mma16816(Oa[2*jp+1], Phi[kk], Bl + 2);
                }
            }
        }
    }

    // ---- finalize: reduce l, normalize, split hi/lo, store ----
    l0r += __shfl_xor_sync(0xffffffffu, l0r, 1);
    l0r += __shfl_xor_sync(0xffffffffu, l0r, 2);
    l1r += __shfl_xor_sync(0xffffffffu, l1r, 1);
    l1r += __shfl_xor_sync(0xffffffffu, l1r, 2);
    float inv0 = 1.0f / l0r, inv1 = 1.0f / l1r;
    #pragma unroll
    for (int j = 0; j < 16; j++) {
        int col = 8 * j + 2 * tig;
        size_t i0 = base + (size_t)grow0 * DD + col;
        size_t i1 = base + (size_t)grow1 * DD + col;
        float v00 = Oa[j][0] * inv0, v01 = Oa[j][1] * inv0;
        float v10 = Oa[j][2] * inv1, v11 = Oa[j][3] * inv1;
        __nv_bfloat16 h00 = __float2bfloat16(v00), h01 = __float2bfloat16(v01);
        __nv_bfloat16 h10 = __float2bfloat16(v10), h11 = __float2bfloat16(v11);
        __nv_bfloat162 p0 = __halves2bfloat162(h00, h01);
        __nv_bfloat162 p1 = __halves2bfloat162(h10, h11);
        *(uint32_t*)(Ohi + i0) = *(uint32_t*)&p0;
        *(uint32_t*)(Ohi + i1) = *(uint32_t*)&p1;
        *(uint32_t*)(Olo + i0) = pack_bf2(v00 - __bfloat162float(h00), v01 - __bfloat162float(h01));
        *(uint32_t*)(Olo + i1) = pack_bf2(v10 - __bfloat162float(h10), v11 - __bfloat162float(h11));
    }
}

// ---------------- launch -----------------------------------------------------
extern "C" void kernel_launch(void* const* d_in, const int* in_sizes, int n_in,
                              void* d_out, int out_size) {
    const float* x        = (const float*)d_in[0];
    const float* W_q      = (const float*)d_in[1];
    const float* W_k      = (const float*)d_in[2];
    const float* W_v      = (const float*)d_in[3];
    const float* W_o      = (const float*)d_in[4];
    const float* ln_attn_g= (const float*)d_in[5];
    const float* ln_attn_b= (const float*)d_in[6];
    const float* fc1_w    = (const float*)d_in[7];
    const float* fc1_b    = (const float*)d_in[8];
    const float* fc2_w    = (const float*)d_in[9];
    const float* fc2_b    = (const float*)d_in[10];
    const float* ln_mlp_g = (const float*)d_in[11];
    const float* ln_mlp_b = (const float*)d_in[12];
    float* out = (float*)d_out;

    float *x2, *part;
    __nv_bfloat16 *h1h, *h1l, *h2h, *h2l, *th, *tl, *aoh, *aol;
    __nv_bfloat16 *qhi, *qlo, *khi, *klo, *vhi, *vlo;
    __nv_bfloat16 *wqh, *wql, *wkh, *wkl, *wvh, *wvl, *woh, *wol, *f1h, *f1l, *f2h, *f2l;
    cudaGetSymbolAddress((void**)&x2,  g_x2);
    cudaGetSymbolAddress((void**)&part, g_part);
    cudaGetSymbolAddress((void**)&h1h, g_h1h); cudaGetSymbolAddress((void**)&h1l, g_h1l);
    cudaGetSymbolAddress((void**)&h2h, g_h2h); cudaGetSymbolAddress((void**)&h2l, g_h2l);
    cudaGetSymbolAddress((void**)&th,  g_th);  cudaGetSymbolAddress((void**)&tl,  g_tl);
    cudaGetSymbolAddress((void**)&aoh, g_aoh); cudaGetSymbolAddress((void**)&aol, g_aol);
    cudaGetSymbolAddress((void**)&qhi, g_qhi); cudaGetSymbolAddress((void**)&qlo, g_qlo);
    cudaGetSymbolAddress((void**)&khi, g_khi); cudaGetSymbolAddress((void**)&klo, g_klo);
    cudaGetSymbolAddress((void**)&vhi, g_vhi); cudaGetSymbolAddress((void**)&vlo, g_vlo);
    cudaGetSymbolAddress((void**)&wqh, g_wqh); cudaGetSymbolAddress((void**)&wql, g_wql);
    cudaGetSymbolAddress((void**)&wkh, g_wkh); cudaGetSymbolAddress((void**)&wkl, g_wkl);
    cudaGetSymbolAddress((void**)&wvh, g_wvh); cudaGetSymbolAddress((void**)&wvl, g_wvl);
    cudaGetSymbolAddress((void**)&woh, g_woh); cudaGetSymbolAddress((void**)&wol, g_wol);
    cudaGetSymbolAddress((void**)&f1h, g_f1h); cudaGetSymbolAddress((void**)&f1l, g_f1l);
    cudaGetSymbolAddress((void**)&f2h, g_f2h); cudaGetSymbolAddress((void**)&f2l, g_f2l);

    // 0) split all six weights to bf16 hi/lo in one launch
    split6<<<1152, 256>>>(W_q, W_k, W_v, W_o, fc1_w, fc2_w,
                          wqh, wql, wkh, wkl, wvh, wvl,
                          woh, wol, f1h, f1l, f2h, f2l);

    // 1) LN -> bf16 hi/lo
    ln_kernel<<<MM/8, 256>>>(x, ln_attn_g, ln_attn_b, h1h, h1l);

    // 2) fused QKV projection (pipelined tensor core, fused RoPE/scale/split)
    const float qscale = 0.08838834764831845f;  // 1/sqrt(128)
    cudaFuncSetAttribute(qkv_mm, cudaFuncAttributeMaxDynamicSharedMemorySize, MM3_SMEM);
    qkv_mm<<<dim3(48, MM/128), 256, MM3_SMEM>>>(qscale);

    // 3) causal flash attention (2 CTAs/SM, Qlo in smem, descending work order)
    cudaFuncSetAttribute(fa_mma, cudaFuncAttributeMaxDynamicSharedMemorySize, FA_SMEM);
    fa_mma<<<1024, 128, FA_SMEM>>>(qhi, qlo, khi, klo, vhi, vlo, aoh, aol);

    // 4) O-projection via split-K (4 x 512, pipelined), then reduce + residual
    cudaFuncSetAttribute(mm3<6,true,true>,  cudaFuncAttributeMaxDynamicSharedMemorySize, MM3_SMEM);
    cudaFuncSetAttribute(mm3<6,false,true>, cudaFuncAttributeMaxDynamicSharedMemorySize, MM3_SMEM);
    cudaFuncSetAttribute(mm3<4,false,true>, cudaFuncAttributeMaxDynamicSharedMemorySize, MM3_SMEM);
    mm3<6,true,true><<<dim3(4, MM/64), 256, MM3_SMEM>>>(aoh, aol, woh, wol, nullptr, nullptr, part, nullptr, nullptr, MM, EE, HD, 512, 1.0f);
    reduce_k<4,false><<<(MM*EE)/1024, 256>>>(part, x, nullptr, x2);

    // 5) LN -> bf16 hi/lo
    ln_kernel<<<MM/8, 256>>>(x2, ln_mlp_g, ln_mlp_b, h2h, h2l);

    // 6) MLP: fc1 (pipelined, HALFM, fused bias+GELU+split), fc2 split-K 4x128
    mm3<4,false,true><<<dim3(DHH/128, MM/64), 256, MM3_SMEM>>>(h2h, h2l, f1h, f1l, fc1_b, nullptr, nullptr, th, tl, MM, DHH, EE, EE, 1.0f);
    mm3<6,false,true><<<dim3(4, MM/64), 256, MM3_SMEM>>>(th, tl, f2h, f2l, nullptr, nullptr, part, nullptr, nullptr, MM, EE, DHH, 128, 1.0f);
    reduce_k<4,true><<<(MM*EE)/1024, 256>>>(part, x2, fc2_b, out);
}

// round 15
// speedup vs baseline: 1.0019x; 1.0019x over previous
#include <cuda_runtime.h>
#include <cuda_bf16.h>
#include <math.h>
#include <stdint.h>

#define BB 2
#define SS 2048
#define EE 128
#define HH 16
#define DD 128
#define DHH 512
#define MM (BB*SS)     // 4096 rows
#define HD (HH*DD)     // 2048

// ---------------- scratch (static __device__, no allocation) ----------------
__device__ float g_x2[MM*EE];
__device__ float g_part[4*MM*EE];
__device__ __nv_bfloat16 g_h1h[MM*EE],  g_h1l[MM*EE];
__device__ __nv_bfloat16 g_h2h[MM*EE],  g_h2l[MM*EE];
__device__ __nv_bfloat16 g_th [MM*DHH], g_tl [MM*DHH];
__device__ __nv_bfloat16 g_aoh[MM*HD],  g_aol[MM*HD];
__device__ __nv_bfloat16 g_qhi[MM*HD],  g_qlo[MM*HD];
__device__ __nv_bfloat16 g_khi[MM*HD],  g_klo[MM*HD];
__device__ __nv_bfloat16 g_vhi[MM*HD],  g_vlo[MM*HD];
__device__ __nv_bfloat16 g_wqh[EE*HD],  g_wql[EE*HD];
__device__ __nv_bfloat16 g_wkh[EE*HD],  g_wkl[EE*HD];
__device__ __nv_bfloat16 g_wvh[EE*HD],  g_wvl[EE*HD];
__device__ __nv_bfloat16 g_woh[HD*EE],  g_wol[HD*EE];
__device__ __nv_bfloat16 g_f1h[EE*DHH], g_f1l[EE*DHH];
__device__ __nv_bfloat16 g_f2h[DHH*EE], g_f2l[DHH*EE];

// ======================= warp MMA helpers (baseline PTX) =====================
__device__ __forceinline__ uint32_t smem_u32(const void* p) {
    uint32_t a;
    asm("{ .reg .u64 t; cvta.to.shared.u64 t, %1; cvt.u32.u64 %0, t; }"
        : "=r"(a) : "l"(p));
    return a;
}
__device__ __forceinline__ void mma16816(float* c, const uint32_t* a, const uint32_t* b) {
    asm volatile(
        "mma.sync.aligned.m16n8k16.row.col.f32.bf16.bf16.f32 "
        "{%0,%1,%2,%3}, {%4,%5,%6,%7}, {%8,%9}, {%0,%1,%2,%3};"
        : "+f"(c[0]), "+f"(c[1]), "+f"(c[2]), "+f"(c[3])
        : "r"(a[0]), "r"(a[1]), "r"(a[2]), "r"(a[3]), "r"(b[0]), "r"(b[1]));
}
__device__ __forceinline__ void ldsm_x4(uint32_t* r, uint32_t addr) {
    asm volatile("ldmatrix.sync.aligned.m8n8.x4.shared.b16 {%0,%1,%2,%3}, [%4];"
        : "=r"(r[0]), "=r"(r[1]), "=r"(r[2]), "=r"(r[3]) : "r"(addr));
}
__device__ __forceinline__ void ldsm_x4_t(uint32_t* r, uint32_t addr) {
    asm volatile("ldmatrix.sync.aligned.m8n8.x4.trans.shared.b16 {%0,%1,%2,%3}, [%4];"
        : "=r"(r[0]), "=r"(r[1]), "=r"(r[2]), "=r"(r[3]) : "r"(addr));
}
__device__ __forceinline__ uint32_t pack_bf2(float a, float b) {
    __nv_bfloat162 h = __halves2bfloat162(__float2bfloat16(a), __float2bfloat16(b));
    return *(uint32_t*)&h;
}
__device__ __forceinline__ void cp16(uint32_t smem_addr, const void* gptr) {
    asm volatile("cp.async.cg.shared.global [%0], [%1], 16;"
        :: "r"(smem_addr), "l"(gptr) : "memory");
}
#define CP_COMMIT() asm volatile("cp.async.commit_group;" ::: "memory")
#define CP_WAIT(n)  asm volatile("cp.async.wait_group %0;" :: "n"(n) : "memory")

// 256B-row swizzle (B tiles, FA tiles); 128B-row swizzle (A tiles)
__device__ __forceinline__ uint32_t boff(int r, int cbyte) {
    return (uint32_t)(r * 256 + (cbyte ^ ((r & 7) << 4)));
}
__device__ __forceinline__ uint32_t aoff(int r, int cbyte) {
    return (uint32_t)(r * 128 + (cbyte ^ ((r & 7) << 4)));
}

// ---------------- fp32 -> bf16 hi/lo split: all six weights in ONE launch ----
__global__ void split6(const float* __restrict__ a0, const float* __restrict__ a1,
                       const float* __restrict__ a2, const float* __restrict__ a3,
                       const float* __restrict__ a4, const float* __restrict__ a5,
                       __nv_bfloat16* h0, __nv_bfloat16* l0,
                       __nv_bfloat16* h1, __nv_bfloat16* l1,
                       __nv_bfloat16* h2, __nv_bfloat16* l2,
                       __nv_bfloat16* h3, __nv_bfloat16* l3,
                       __nv_bfloat16* h4, __nv_bfloat16* l4,
                       __nv_bfloat16* h5, __nv_bfloat16* l5) {
    const float* ws[6] = {a0, a1, a2, a3, a4, a5};
    __nv_bfloat16* hs[6] = {h0, h1, h2, h3, h4, h5};
    __nv_bfloat16* ls[6] = {l0, l1, l2, l3, l4, l5};
    int b = blockIdx.x, wi, off;
    if (b < 1024) { wi = b >> 8;       off = (b & 255) * 1024; }
    else          { b -= 1024; wi = 4 + (b >> 6); off = (b & 63) * 1024; }
    int i = off + threadIdx.x * 4;
    float4 v = *(const float4*)(ws[wi] + i);
    __nv_bfloat16 b0 = __float2bfloat16(v.x), b1 = __float2bfloat16(v.y);
    __nv_bfloat16 b2 = __float2bfloat16(v.z), b3 = __float2bfloat16(v.w);
    __nv_bfloat162 hh01 = __halves2bfloat162(b0, b1), hh23 = __halves2bfloat162(b2, b3);
    *(uint2*)(hs[wi] + i) = make_uint2(*(uint32_t*)&hh01, *(uint32_t*)&hh23);
    uint32_t l01 = pack_bf2(v.x - __bfloat162float(b0), v.y - __bfloat162float(b1));
    uint32_t l23 = pack_bf2(v.z - __bfloat162float(b2), v.w - __bfloat162float(b3));
    *(uint2*)(ls[wi] + i) = make_uint2(l01, l23);
}

// ---------------- split-K reduce: out = resid (+bias) + sum partials --------
template<int NS, bool BIAS>
__global__ void reduce_k(const float* __restrict__ part, const float* __restrict__ resid,
                         const float* __restrict__ bias, float* __restrict__ out) {
    int i = (blockIdx.x * 256 + threadIdx.x) * 4;
    float4 acc = *(const float4*)(resid + i);
    if (BIAS) {
        float4 bv = *(const float4*)(bias + (i & (EE - 1)));
        acc.x += bv.x; acc.y += bv.y; acc.z += bv.z; acc.w += bv.w;
    }
    #pragma unroll
    for (int z = 0; z < NS; z++) {
        float4 p = *(const float4*)(part + (size_t)z * (MM * EE) + i);
        acc.x += p.x; acc.y += p.y; acc.z += p.z; acc.w += p.w;
    }
    *(float4*)(out + i) = acc;
}

// ---------------- LayerNorm: one warp per row, bf16 hi/lo out ---------------
__global__ void ln_kernel(const float* __restrict__ x, const float* __restrict__ g,
                          const float* __restrict__ b,
                          __nv_bfloat16* __restrict__ ohi, __nv_bfloat16* __restrict__ olo) {
    int warp = threadIdx.x >> 5, lane = threadIdx.x & 31;
    int row = blockIdx.x * 8 + warp;
    float4 v = ((const float4*)(x + (size_t)row * EE))[lane];
    float s = v.x + v.y + v.z + v.w;
    #pragma unroll
    for (int o = 16; o; o >>= 1) s += __shfl_xor_sync(0xffffffffu, s, o);
    float mu = s * (1.0f / EE);
    float d0 = v.x - mu, d1 = v.y - mu, d2 = v.z - mu, d3 = v.w - mu;
    float q = d0*d0 + d1*d1 + d2*d2 + d3*d3;
    #pragma unroll
    for (int o = 16; o; o >>= 1) q += __shfl_xor_sync(0xffffffffu, q, o);
    float inv = rsqrtf(q * (1.0f / EE) + 1e-5f);
    float4 gg = ((const float4*)g)[lane];
    float4 bb = ((const float4*)b)[lane];
    float r0 = d0 * inv * gg.x + bb.x;
    float r1 = d1 * inv * gg.y + bb.y;
    float r2 = d2 * inv * gg.z + bb.z;
    float r3 = d3 * inv * gg.w + bb.w;
    __nv_bfloat16 h0 = __float2bfloat16(r0), h1 = __float2bfloat16(r1);
    __nv_bfloat16 h2 = __float2bfloat16(r2), h3 = __float2bfloat16(r3);
    __nv_bfloat162 hh01 = __halves2bfloat162(h0, h1), hh23 = __halves2bfloat162(h2, h3);
    size_t base = (size_t)row * EE + lane * 4;
    *(uint2*)(ohi + base) = make_uint2(*(uint32_t*)&hh01, *(uint32_t*)&hh23);
    uint32_t l01 = pack_bf2(r0 - __bfloat162float(h0), r1 - __bfloat162float(h1));
    uint32_t l23 = pack_bf2(r2 - __bfloat162float(h2), r3 - __bfloat162float(h3));
    *(uint2*)(olo + base) = make_uint2(l01, l23);
}

// ---- fused split-K reduce + LayerNorm (O-proj epilogue + LN2 in one pass) --
// acc = resid + sum partials (same order as reduce_k -> bit-identical x2);
// writes x2 (residual for fc2) AND LN(acc) as bf16 hi/lo.
__global__ void reduce_ln(const float* __restrict__ part, const float* __restrict__ resid,
                          const float* __restrict__ g, const float* __restrict__ b,
                          float* __restrict__ x2out,
                          __nv_bfloat16* __restrict__ ohi, __nv_bfloat16* __restrict__ olo) {
    int warp = threadIdx.x >> 5, lane = threadIdx.x & 31;
    int row = blockIdx.x * 8 + warp;
    size_t i = (size_t)row * EE + lane * 4;
    float4 v = *(const float4*)(resid + i);
    #pragma unroll
    for (int z = 0; z < 4; z++) {
        float4 p = *(const float4*)(part + (size_t)z * (MM * EE) + i);
        v.x += p.x; v.y += p.y; v.z += p.z; v.w += p.w;
    }
    *(float4*)(x2out + i) = v;
    float s = v.x + v.y + v.z + v.w;
    #pragma unroll
    for (int o = 16; o; o >>= 1) s += __shfl_xor_sync(0xffffffffu, s, o);
    float mu = s * (1.0f / EE);
    float d0 = v.x - mu, d1 = v.y - mu, d2 = v.z - mu, d3 = v.w - mu;
    float q = d0*d0 + d1*d1 + d2*d2 + d3*d3;
    #pragma unroll
    for (int o = 16; o; o >>= 1) q += __shfl_xor_sync(0xffffffffu, q, o);
    float inv = rsqrtf(q * (1.0f / EE) + 1e-5f);
    float4 gg = ((const float4*)g)[lane];
    float4 bb = ((const float4*)b)[lane];
    float r0 = d0 * inv * gg.x + bb.x;
    float r1 = d1 * inv * gg.y + bb.y;
    float r2 = d2 * inv * gg.z + bb.z;
    float r3 = d3 * inv * gg.w + bb.w;
    __nv_bfloat16 h0 = __float2bfloat16(r0), h1 = __float2bfloat16(r1);
    __nv_bfloat16 h2 = __float2bfloat16(r2), h3 = __float2bfloat16(r3);
    __nv_bfloat162 hh01 = __halves2bfloat162(h0, h1), hh23 = __halves2bfloat162(h2, h3);
    *(uint2*)(ohi + i) = make_uint2(*(uint32_t*)&hh01, *(uint32_t*)&hh23);
    uint32_t l01 = pack_bf2(r0 - __bfloat162float(h0), r1 - __bfloat162float(h1));
    uint32_t l23 = pack_bf2(r2 - __bfloat162float(h2), r3 - __bfloat162float(h3));
    *(uint2*)(olo + i) = make_uint2(l01, l23);
}

// =============== shared smem layout for projection GEMMs (2 stages) =========
#define MM3_AHI 0u
#define MM3_ALO 16384u
#define MM3_BHI 32768u
#define MM3_BLO 49152u
#define MM3_STAGE 65536u
#define MM3_SMEM 131072

// =============== fused QKV projection (pipelined, bf16x3) ===================
__global__ __launch_bounds__(256, 1)
void qkv_mm(float qscale)
{
    extern __shared__ char sm[];
    uint32_t sb = smem_u32(sm);
    const int tid = threadIdx.x;
    const int w = tid >> 5, ln = tid & 31;
    const int tig = ln & 3, gid = ln >> 2;
    const int mi = blockIdx.x >> 4;
    const int n0 = (blockIdx.x & 15) * 128;
    const int m0 = blockIdx.y * 128;
    const __nv_bfloat16* Bh_ = (mi == 0) ? g_wqh : (mi == 1) ? g_wkh : g_wvh;
    const __nv_bfloat16* Bl_ = (mi == 0) ? g_wql : (mi == 1) ? g_wkl : g_wvl;
    __nv_bfloat16* Oh_ = (mi == 0) ? g_qhi : (mi == 1) ? g_khi : g_vhi;
    __nv_bfloat16* Ol_ = (mi == 0) ? g_qlo : (mi == 1) ? g_klo : g_vlo;
    const float scale = (mi == 0) ? qscale : 1.0f;

    float C[16][4];
    #pragma unroll
    for (int j = 0; j < 16; j++)
        #pragma unroll
        for (int e = 0; e < 4; e++) C[j][e] = 0.f;

    const int arow = 16 * w + ((ln >> 3) & 1) * 8 + (ln & 7);
    const int akb  = (ln >> 4) * 16;
    const int brow = ((ln >> 3) & 1) * 8 + (ln & 7);
    const int bcb  = (ln >> 4) << 4;

    // prologue: prefetch k-iter 0 into stage 0
    for (int f = tid; f < 1024; f += 256) {
        int r = f >> 3, seg = f & 7;
        size_t g = (size_t)(m0 + r) * EE + seg * 8;
        uint32_t so = aoff(r, seg * 16);
        cp16(sb + MM3_AHI + so, g_h1h + g);
        cp16(sb + MM3_ALO + so, g_h1l + g);
    }
    for (int f = tid; f < 1024; f += 256) {
        int r = f >> 4, seg = f & 15;
        size_t g = (size_t)r * HD + n0 + seg * 8;
        uint32_t so = boff(r, seg * 16);
        cp16(sb + MM3_BHI + so, Bh_ + g);
        cp16(sb + MM3_BLO + so, Bl_ + g);
    }
    CP_COMMIT();

    #pragma unroll
    for (int it = 0; it < 2; it++) {
        uint32_t st = (uint32_t)(it & 1) * MM3_STAGE;
        __syncthreads();
        if (it == 0) {
            for (int f = tid; f < 1024; f += 256) {
                int r = f >> 3, seg = f & 7;
                size_t g = (size_t)(m0 + r) * EE + 64 + seg * 8;
                uint32_t so = aoff(r, seg * 16);
                cp16(sb + MM3_STAGE + MM3_AHI + so, g_h1h + g);
                cp16(sb + MM3_STAGE + MM3_ALO + so, g_h1l + g);
            }
            for (int f = tid; f < 1024; f += 256) {
                int r = f >> 4, seg = f & 15;
                size_t g = (size_t)(64 + r) * HD + n0 + seg * 8;
                uint32_t so = boff(r, seg * 16);
                cp16(sb + MM3_STAGE + MM3_BHI + so, Bh_ + g);
                cp16(sb + MM3_STAGE + MM3_BLO + so, Bl_ + g);
            }
            CP_COMMIT();
            CP_WAIT(1);
        } else {
            CP_WAIT(0);
        }
        __syncthreads();

        uint32_t Ah[4][4], Al[4][4];
        #pragma unroll
        for (int kk = 0; kk < 4; kk++) {
            uint32_t off = aoff(arow, kk * 32 + akb);
            ldsm_x4(Ah[kk], sb + st + MM3_AHI + off);
            ldsm_x4(Al[kk], sb + st + MM3_ALO + off);
        }
        #pragma unroll
        for (int jp = 0; jp < 8; jp++) {
            int ncb = 32 * jp;
            #pragma unroll
            for (int kk = 0; kk < 4; kk++) {
                uint32_t off = boff(16 * kk + brow, ncb + bcb);
                uint32_t Bh[4], Bl[4];
                ldsm_x4_t(Bh, sb + st + MM3_BHI + off);
                mma16816(C[2*jp],   Ah[kk], Bh);
                mma16816(C[2*jp+1], Ah[kk], Bh + 2);
                mma16816(C[2*jp],   Al[kk], Bh);
                mma16816(C[2*jp+1], Al[kk], Bh + 2);
                ldsm_x4_t(Bl, sb + st + MM3_BLO + off);
                mma16816(C[2*jp],   Ah[kk], Bl);
                mma16816(C[2*jp+1], Ah[kk], Bl + 2);
            }
        }
    }

    // epilogue: scale, RoPE (Q/K), bf16 hi/lo split to (B,H,S,D)
    const int r0 = m0 + 16 * w + gid;
    const int r1 = r0 + 8;
    int b_ = r0 >> 11, s0 = r0 & 2047, s1 = r1 & 2047;
    #pragma unroll
    for (int j = 0; j < 16; j++) {
        int colg = n0 + 8 * j + 2 * tig;
        int h = colg >> 7, d = colg & 127;
        float o00 = C[j][0] * scale, o01 = C[j][1] * scale;
        float o10 = C[j][2] * scale, o11 = C[j][3] * scale;
        if (mi < 2) {
            int t2 = d >> 1;
            float f = expf((float)t2 * -0.14391157f);
            float si0, co0, si1, co1;
            sincosf((float)s0 * f, &si0, &co0);
            sincosf((float)s1 * f, &si1, &co1);
            float a = o00 * co0 - o01 * si0, b2 = o00 * si0 + o01 * co0;
            o00 = a; o01 = b2;
            a = o10 * co1 - o11 * si1; b2 = o10 * si1 + o11 * co1;
            o10 = a; o11 = b2;
        }
        size_t oi0 = (((size_t)(b_ * HH + h) * SS + s0) * DD + d);
        size_t oi1 = (((size_t)(b_ * HH + h) * SS + s1) * DD + d);
        __nv_bfloat16 h00 = __float2bfloat16(o00), h01 = __float2bfloat16(o01);
        __nv_bfloat16 h10 = __float2bfloat16(o10), h11 = __float2bfloat16(o11);
        __nv_bfloat162 p0 = __halves2bfloat162(h00, h01);
        __nv_bfloat162 p1 = __halves2bfloat162(h10, h11);
        *(uint32_t*)(Oh_ + oi0) = *(uint32_t*)&p0;
        *(uint32_t*)(Oh_ + oi1) = *(uint32_t*)&p1;
        *(uint32_t*)(Ol_ + oi0) = pack_bf2(o00 - __bfloat162float(h00), o01 - __bfloat162float(h01));
        *(uint32_t*)(Ol_ + oi1) = pack_bf2(o10 - __bfloat162float(h10), o11 - __bfloat162float(h11));
    }
}

// =============== bf16x3 tensor-core GEMM (pipelined) ========================
// MODE 4: gelu(acc + bias) -> bf16 hi/lo               (fc1)
// MODE 6: split-K partial: fp32 to out + blockIdx.x*M*N, k in [bx*kspl, +kspl)
template<int MODE, bool AG, bool HALFM>
__global__ __launch_bounds__(256)
void mm3(const __nv_bfloat16* __restrict__ Ahi, const __nv_bfloat16* __restrict__ Alo,
         const __nv_bfloat16* __restrict__ Bhi, const __nv_bfloat16* __restrict__ Blo,
         const float* __restrict__ bias, const float* __restrict__ resid,
         float* __restrict__ out,
         __nv_bfloat16* __restrict__ ohi, __nv_bfloat16* __restrict__ olo,
         int M, int N, int K, int kspl, float qscale)
{
    extern __shared__ char sm[];
    uint32_t sb = smem_u32(sm);
    constexpr int MT = HALFM ? 64 : 128;
    constexpr int NJ = HALFM ? 8 : 16;
    const int tid = threadIdx.x;
    const int w = tid >> 5, ln = tid & 31;
    const int tig = ln & 3, gid = ln >> 2;
    const int wr = HALFM ? (w & 3) : w;
    const int wc = HALFM ? (w >> 2) * 64 : 0;
    const int m0 = blockIdx.y * MT;
    const int n0 = (MODE == 6) ? 0 : blockIdx.x * 128;
    const int kb = (MODE == 6) ? blockIdx.x * kspl : 0;
    const int ke = (MODE == 6) ? kb + kspl : K;
    const int niter = (ke - kb) >> 6;

    float C[NJ][4];
    #pragma unroll
    for (int j = 0; j < NJ; j++)
        #pragma unroll
        for (int e = 0; e < 4; e++) C[j][e] = 0.f;

    const int arow = 16 * wr + ((ln >> 3) & 1) * 8 + (ln & 7);
    const int akb  = (ln >> 4) * 16;
    const int brow = ((ln >> 3) & 1) * 8 + (ln & 7);
    const int bcb  = (ln >> 4) << 4;

    // prologue: prefetch iter 0
    {
        int k0 = kb;
        for (int f = tid; f < MT * 8; f += 256) {
            int r = f >> 3, seg = f & 7;
            size_t g;
            if (!AG) {
                g = (size_t)(m0 + r) * K + k0 + seg * 8;
            } else {
                int rr = m0 + r;
                int b_ = rr >> 11, s_ = rr & 2047;
                int kk = k0 + seg * 8;
                g = ((size_t)(b_ * HH + (kk >> 7)) * SS + s_) * DD + (kk & 127);
            }
            uint32_t so = aoff(r, seg * 16);
            cp16(sb + MM3_AHI + so, Ahi + g);
            cp16(sb + MM3_ALO + so, Alo + g);
        }
        for (int f = tid; f < 1024; f += 256) {
            int r = f >> 4, seg = f & 15;
            size_t g = (size_t)(k0 + r) * N + n0 + seg * 8;
            uint32_t so = boff(r, seg * 16);
            cp16(sb + MM3_BHI + so, Bhi + g);
            cp16(sb + MM3_BLO + so, Blo + g);
        }
        CP_COMMIT();
    }

    for (int it = 0; it < niter; it++) {
        uint32_t st = (uint32_t)(it & 1) * MM3_STAGE;
        __syncthreads();
        if (it + 1 < niter) {
            int k0 = kb + (it + 1) * 64;
            uint32_t stn = (uint32_t)((it + 1) & 1) * MM3_STAGE;
            for (int f = tid; f < MT * 8; f += 256) {
                int r = f >> 3, seg = f & 7;
                size_t g;
                if (!AG) {
                    g = (size_t)(m0 + r) * K + k0 + seg * 8;
                } else {
                    int rr = m0 + r;
                    int b_ = rr >> 11, s_ = rr & 2047;
                    int kk = k0 + seg * 8;
                    g = ((size_t)(b_ * HH + (kk >> 7)) * SS + s_) * DD + (kk & 127);
                }
                uint32_t so = aoff(r, seg * 16);
                cp16(sb + stn + MM3_AHI + so, Ahi + g);
                cp16(sb + stn + MM3_ALO + so, Alo + g);
            }
            for (int f = tid; f < 1024; f += 256) {
                int r = f >> 4, seg = f & 15;
                size_t g = (size_t)(k0 + r) * N + n0 + seg * 8;
                uint32_t so = boff(r, seg * 16);
                cp16(sb + stn + MM3_BHI + so, Bhi + g);
                cp16(sb + stn + MM3_BLO + so, Blo + g);
            }
            CP_COMMIT();
            CP_WAIT(1);
        } else {
            CP_WAIT(0);
        }
        __syncthreads();

        uint32_t Ah[4][4], Al[4][4];
        #pragma unroll
        for (int kk = 0; kk < 4; kk++) {
            uint32_t off = aoff(arow, kk * 32 + akb);
            ldsm_x4(Ah[kk], sb + st + MM3_AHI + off);
            ldsm_x4(Al[kk], sb + st + MM3_ALO + off);
        }
        #pragma unroll
        for (int jp = 0; jp < NJ / 2; jp++) {
            int ncb = (wc + 16 * jp) * 2;
            #pragma unroll
            for (int kk = 0; kk < 4; kk++) {
                uint32_t off = boff(16 * kk + brow, ncb + bcb);
                uint32_t Bh[4], Bl[4];
                ldsm_x4_t(Bh, sb + st + MM3_BHI + off);
                mma16816(C[2*jp],   Ah[kk], Bh);
                mma16816(C[2*jp+1], Ah[kk], Bh + 2);
                mma16816(C[2*jp],   Al[kk], Bh);
                mma16816(C[2*jp+1], Al[kk], Bh + 2);
                ldsm_x4_t(Bl, sb + st + MM3_BLO + off);
                mma16816(C[2*jp],   Ah[kk], Bl);
                mma16816(C[2*jp+1], Ah[kk], Bl + 2);
            }
        }
    }

    const int r0 = m0 + 16 * wr + gid;
    const int r1 = r0 + 8;
    if (MODE == 6) {
        float* po = out + (size_t)blockIdx.x * M * N;
        #pragma unroll
        for (int j = 0; j < NJ; j++) {
            int colg = wc + 8 * j + 2 * tig;
            size_t i0 = (size_t)r0 * N + colg;
            size_t i1 = (size_t)r1 * N + colg;
            *(float2*)(po + i0) = make_float2(C[j][0], C[j][1]);
            *(float2*)(po + i1) = make_float2(C[j][2], C[j][3]);
        }
    } else if (MODE == 4) {
        #pragma unroll
        for (int j = 0; j < NJ; j++) {
            int colg = n0 + wc + 8 * j + 2 * tig;
            size_t i0 = (size_t)r0 * N + colg;
            size_t i1 = (size_t)r1 * N + colg;
            float v00 = C[j][0], v01 = C[j][1], v10 = C[j][2], v11 = C[j][3];
            float b0 = bias[colg], b1 = bias[colg + 1];
            v00 += b0; v01 += b1; v10 += b0; v11 += b1;
            v00 = 0.5f * v00 * (1.0f + erff(v00 * 0.70710678f));
            v01 = 0.5f * v01 * (1.0f + erff(v01 * 0.70710678f));
            v10 = 0.5f * v10 * (1.0f + erff(v10 * 0.70710678f));
            v11 = 0.5f * v11 * (1.0f + erff(v11 * 0.70710678f));
            __nv_bfloat16 h00 = __float2bfloat16(v00), h01 = __float2bfloat16(v01);
            __nv_bfloat16 h10 = __float2bfloat16(v10), h11 = __float2bfloat16(v11);
            __nv_bfloat162 p0 = __halves2bfloat162(h00, h01);
            __nv_bfloat162 p1 = __halves2bfloat162(h10, h11);
            *(uint32_t*)(ohi + i0) = *(uint32_t*)&p0;
            *(uint32_t*)(ohi + i1) = *(uint32_t*)&p1;
            *(uint32_t*)(olo + i0) = pack_bf2(v00 - __bfloat162float(h00), v01 - __bfloat162float(h01));
            *(uint32_t*)(olo + i1) = pack_bf2(v10 - __bfloat162float(h10), v11 - __bfloat162float(h11));
        }
    }
}

// ============== mma.sync flash attention (bf16x3, 2 CTAs/SM) ================
// CTA: 128 threads, 64 query rows. Grid 1024 (globally-descending work).
// Smem/CTA = 112KB: K [0,32K), V double [32K,96K), Qlo resident [96K,112K).
#define FA_KHI 0u
#define FA_KLO 16384u
#define FA_V0  32768u
#define FA_VST 32768u
#define FA_QLO 98304u
#define FA_SMEM 114688

__device__ __forceinline__ uint32_t fa_off(int r, int cbyte) {
    return (uint32_t)(r * 256 + (cbyte ^ ((r & 7) << 4)));
}

__global__ __launch_bounds__(128, 2)
void fa_mma(const __nv_bfloat16* __restrict__ qhi, const __nv_bfloat16* __restrict__ qlo,
            const __nv_bfloat16* __restrict__ khi, const __nv_bfloat16* __restrict__ klo,
            const __nv_bfloat16* __restrict__ vhi, const __nv_bfloat16* __restrict__ vlo,
            __nv_bfloat16* __restrict__ Ohi, __nv_bfloat16* __restrict__ Olo)
{
    extern __shared__ char sm[];
    uint32_t sb = smem_u32(sm);
    const int tid = threadIdx.x;
    const int w = tid >> 5, ln = tid & 31;
    const int tig = ln & 3, gid = ln >> 2;
    const int bid = blockIdx.x;
    const int m0 = (31 - (bid >> 5)) * 64;    // globally descending work
    const int bh = bid & 31;
    const size_t base = (size_t)bh * SS * DD;

    // ---- stage Q: hi via K region (transient), lo into resident FA_QLO ----
    for (int f = tid; f < 1024; f += 128) {
        int r = f >> 4, c16 = f & 15;
        size_t g = base + (size_t)(m0 + r) * DD + c16 * 8;
        uint32_t so = fa_off(r, c16 * 16);
        *(uint4*)(sm + FA_KHI + so) = *(const uint4*)(qhi + g);
        *(uint4*)(sm + FA_QLO + so) = *(const uint4*)(qlo + g);
    }
    __syncthreads();
    const int qrow = 16 * w + ((ln >> 3) & 1) * 8 + (ln & 7);
    const int qkb  = (ln >> 4) * 16;
    uint32_t Qh[8][4];
    #pragma unroll
    for (int kk = 0; kk < 8; kk++)
        ldsm_x4(Qh[kk], sb + FA_KHI + fa_off(qrow, kk * 32 + qkb));
    __syncthreads();

    float Oa[16][4];
    #pragma unroll
    for (int j = 0; j < 16; j++)
        #pragma unroll
        for (int e = 0; e < 4; e++) Oa[j][e] = 0.f;
    float m0r = -1e30f, m1r = -1e30f, l0r = 0.f, l1r = 0.f;

    const int grow0 = m0 + 16 * w + gid;
    const int grow1 = grow0 + 8;
    const int nk = m0 / 64 + 1;

    // ---- prologue: K(0), V(0) ----
    for (int f = tid; f < 1024; f += 128) {
        int r = f >> 4, c16 = f & 15;
        size_t g = base + (size_t)r * DD + c16 * 8;
        uint32_t so = fa_off(r, c16 * 16);
        cp16(sb + FA_KHI + so, khi + g);
        cp16(sb + FA_KLO + so, klo + g);
        cp16(sb + FA_V0 + so, vhi + g);
        cp16(sb + FA_V0 + 16384 + so, vlo + g);
    }
    CP_COMMIT();

    for (int t = 0; t < nk; t++) {
        int n0 = t * 64;
        uint32_t vb = FA_V0 + (uint32_t)(t & 1) * FA_VST;
        CP_WAIT(0);        // K(t), V(t) resident
        __syncthreads();

        // ---- S = Q K^T (3-term); kk outer, Ql re-loaded per kk ----
        float S[8][4];
        #pragma unroll
        for (int j = 0; j < 8; j++)
            #pragma unroll
            for (int e = 0; e < 4; e++) S[j][e] = 0.f;
        {
            int brow = ((ln >> 4) << 3) + (ln & 7);
            int bkb  = ((ln >> 3) & 1) << 4;
            #pragma unroll
            for (int kk = 0; kk < 8; kk++) {
                uint32_t Qlt[4];
                ldsm_x4(Qlt, sb + FA_QLO + fa_off(qrow, kk * 32 + qkb));
                #pragma unroll
                for (int jp = 0; jp < 4; jp++) {
                    int r_ = 16 * jp + brow;
                    uint32_t off = fa_off(r_, kk * 32 + bkb);
                    uint32_t Bh[4], Bl[4];
                    ldsm_x4(Bh, sb + FA_KHI + off);
                    mma16816(S[2*jp],   Qh[kk], Bh);
                    mma16816(S[2*jp+1], Qh[kk], Bh + 2);
                    mma16816(S[2*jp],   Qlt, Bh);
                    mma16816(S[2*jp+1], Qlt, Bh + 2);
                    ldsm_x4(Bl, sb + FA_KLO + off);
                    mma16816(S[2*jp],   Qh[kk], Bl);
                    mma16816(S[2*jp+1], Qh[kk], Bl + 2);
                }
            }
        }
        __syncthreads();   // all warps done reading K(t)

        // ---- prefetch K(t+1) and V(t+1) (overlaps softmax + PV below) ----
        if (t + 1 < nk) {
            int n1 = n0 + 64;
            uint32_t vbn = FA_V0 + (uint32_t)((t + 1) & 1) * FA_VST;
            for (int f = tid; f < 1024; f += 128) {
                int r = f >> 4, c16 = f & 15;
                size_t g = base + (size_t)(n1 + r) * DD + c16 * 8;
                uint32_t so = fa_off(r, c16 * 16);
                cp16(sb + FA_KHI + so, khi + g);
                cp16(sb + FA_KLO + so, klo + g);
                cp16(sb + vbn + so, vhi + g);
                cp16(sb + vbn + 16384 + so, vlo + g);
            }
            CP_COMMIT();
        }

        // ---- causal mask (diagonal tile only) ----
        if (n0 + 63 > m0 + 16 * w) {
            #pragma unroll
            for (int j = 0; j < 8; j++) {
                int c = n0 + 8 * j + 2 * tig;
                if (c     > grow0) S[j][0] = -1e30f;
                if (c + 1 > grow0) S[j][1] = -1e30f;
                if (c     > grow1) S[j][2] = -1e30f;
                if (c + 1 > grow1) S[j][3] = -1e30f;
            }
        }

        // ---- online softmax ----
        float mx0 = -1e30f, mx1 = -1e30f;
        #pragma unroll
        for (int j = 0; j < 8; j++) {
            mx0 = fmaxf(mx0, fmaxf(S[j][0], S[j][1]));
            mx1 = fmaxf(mx1, fmaxf(S[j][2], S[j][3]));
        }
        mx0 = fmaxf(mx0, __shfl_xor_sync(0xffffffffu, mx0, 1));
        mx0 = fmaxf(mx0, __shfl_xor_sync(0xffffffffu, mx0, 2));
        mx1 = fmaxf(mx1, __shfl_xor_sync(0xffffffffu, mx1, 1));
        mx1 = fmaxf(mx1, __shfl_xor_sync(0xffffffffu, mx1, 2));
        float mn0 = fmaxf(m0r, mx0), mn1 = fmaxf(m1r, mx1);
        bool nochg = (mn0 == m0r) && (mn1 == m1r);
        float a0 = nochg ? 1.f : __expf(m0r - mn0);
        float a1 = nochg ? 1.f : __expf(m1r - mn1);
        m0r = mn0; m1r = mn1;
        l0r *= a0; l1r *= a1;

        uint32_t Phi[4][4], Plo[4][4];
        float ls0 = 0.f, ls1 = 0.f;
        #pragma unroll
        for (int j = 0; j < 8; j++) {
            float p0 = __expf(S[j][0] - mn0);
            float p1 = __expf(S[j][1] - mn0);
            float p2 = __expf(S[j][2] - mn1);
            float p3 = __expf(S[j][3] - mn1);
            ls0 += p0 + p1; ls1 += p2 + p3;
            __nv_bfloat16 h0 = __float2bfloat16(p0);
            __nv_bfloat16 h1 = __float2bfloat16(p1);
            __nv_bfloat16 h2 = __float2bfloat16(p2);
            __nv_bfloat16 h3 = __float2bfloat16(p3);
            int kk = j >> 1, q = (j & 1) * 2;
            __nv_bfloat162 hh01 = __halves2bfloat162(h0, h1);
            __nv_bfloat162 hh23 = __halves2bfloat162(h2, h3);
            Phi[kk][q]     = *(uint32_t*)&hh01;
            Phi[kk][q + 1] = *(uint32_t*)&hh23;
            Plo[kk][q]     = pack_bf2(p0 - __bfloat162float(h0), p1 - __bfloat162float(h1));
            Plo[kk][q + 1] = pack_bf2(p2 - __bfloat162float(h2), p3 - __bfloat162float(h3));
        }
        l0r += ls0; l1r += ls1;

        if (!__all_sync(0xffffffffu, nochg)) {
            #pragma unroll
            for (int j = 0; j < 16; j++) {
                Oa[j][0] *= a0; Oa[j][1] *= a0;
                Oa[j][2] *= a1; Oa[j][3] *= a1;
            }
        }

        // ---- O += P V (3-term) ----
        {
            int vrow = ((ln >> 3) & 1) * 8 + (ln & 7);
            int vcb  = (ln >> 4) << 4;
            #pragma unroll
            for (int jp = 0; jp < 8; jp++) {
                #pragma unroll
                for (int kk = 0; kk < 4; kk++) {
                    int r_ = 16 * kk + vrow;
                    uint32_t off = fa_off(r_, 32 * jp + vcb);
                    uint32_t Bh[4], Bl[4];
                    ldsm_x4_t(Bh, sb + vb + off);
                    mma16816(Oa[2*jp],   Phi[kk], Bh);
                    mma16816(Oa[2*jp+1], Phi[kk], Bh + 2);
                    mma16816(Oa[2*jp],   Plo[kk], Bh);
                    mma16816(Oa[2*jp+1], Plo[kk], Bh + 2);
                    ldsm_x4_t(Bl, sb + vb + 16384 + off);
                    mma16816(Oa[2*jp],   Phi[kk], Bl);
                    mma16816(Oa[2*jp+1], Phi[kk], Bl + 2);
                }
            }
        }
    }

    // ---- finalize: reduce l, normalize, split hi/lo, store ----
    l0r += __shfl_xor_sync(0xffffffffu, l0r, 1);
    l0r += __shfl_xor_sync(0xffffffffu, l0r, 2);
    l1r += __shfl_xor_sync(0xffffffffu, l1r, 1);
    l1r += __shfl_xor_sync(0xffffffffu, l1r, 2);
    float inv0 = 1.0f / l0r, inv1 = 1.0f / l1r;
    #pragma unroll
    for (int j = 0; j < 16; j++) {
        int col = 8 * j + 2 * tig;
        size_t i0 = base + (size_t)grow0 * DD + col;
        size_t i1 = base + (size_t)grow1 * DD + col;
        float v00 = Oa[j][0] * inv0, v01 = Oa[j][1] * inv0;
        float v10 = Oa[j][2] * inv1, v11 = Oa[j][3] * inv1;
        __nv_bfloat16 h00 = __float2bfloat16(v00), h01 = __float2bfloat16(v01);
        __nv_bfloat16 h10 = __float2bfloat16(v10), h11 = __float2bfloat16(v11);
        __nv_bfloat162 p0 = __halves2bfloat162(h00, h01);
        __nv_bfloat162 p1 = __halves2bfloat162(h10, h11);
        *(uint32_t*)(Ohi + i0) = *(uint32_t*)&p0;
        *(uint32_t*)(Ohi + i1) = *(uint32_t*)&p1;
        *(uint32_t*)(Olo + i0) = pack_bf2(v00 - __bfloat162float(h00), v01 - __bfloat162float(h01));
        *(uint32_t*)(Olo + i1) = pack_bf2(v10 - __bfloat162float(h10), v11 - __bfloat162float(h11));
    }
}

// ---------------- launch -----------------------------------------------------
extern "C" void kernel_launch(void* const* d_in, const int* in_sizes, int n_in,
                              void* d_out, int out_size) {
    const float* x        = (const float*)d_in[0];
    const float* W_q      = (const float*)d_in[1];
    const float* W_k      = (const float*)d_in[2];
    const float* W_v      = (const float*)d_in[3];
    const float* W_o      = (const float*)d_in[4];
    const float* ln_attn_g= (const float*)d_in[5];
    const float* ln_attn_b= (const float*)d_in[6];
    const float* fc1_w    = (const float*)d_in[7];
    const float* fc1_b    = (const float*)d_in[8];
    const float* fc2_w    = (const float*)d_in[9];
    const float* fc2_b    = (const float*)d_in[10];
    const float* ln_mlp_g = (const float*)d_in[11];
    const float* ln_mlp_b = (const float*)d_in[12];
    float* out = (float*)d_out;

    float *x2, *part;
    __nv_bfloat16 *h1h, *h1l, *h2h, *h2l, *th, *tl, *aoh, *aol;
    __nv_bfloat16 *qhi, *qlo, *khi, *klo, *vhi, *vlo;
    __nv_bfloat16 *wqh, *wql, *wkh, *wkl, *wvh, *wvl, *woh, *wol, *f1h, *f1l, *f2h, *f2l;
    cudaGetSymbolAddress((void**)&x2,  g_x2);
    cudaGetSymbolAddress((void**)&part, g_part);
    cudaGetSymbolAddress((void**)&h1h, g_h1h); cudaGetSymbolAddress((void**)&h1l, g_h1l);
    cudaGetSymbolAddress((void**)&h2h, g_h2h); cudaGetSymbolAddress((void**)&h2l, g_h2l);
    cudaGetSymbolAddress((void**)&th,  g_th);  cudaGetSymbolAddress((void**)&tl,  g_tl);
    cudaGetSymbolAddress((void**)&aoh, g_aoh); cudaGetSymbolAddress((void**)&aol, g_aol);
    cudaGetSymbolAddress((void**)&qhi, g_qhi); cudaGetSymbolAddress((void**)&qlo, g_qlo);
    cudaGetSymbolAddress((void**)&khi, g_khi); cudaGetSymbolAddress((void**)&klo, g_klo);
    cudaGetSymbolAddress((void**)&vhi, g_vhi); cudaGetSymbolAddress((void**)&vlo, g_vlo);
    cudaGetSymbolAddress((void**)&wqh, g_wqh); cudaGetSymbolAddress((void**)&wql, g_wql);
    cudaGetSymbolAddress((void**)&wkh, g_wkh); cudaGetSymbolAddress((void**)&wkl, g_wkl);
    cudaGetSymbolAddress((void**)&wvh, g_wvh); cudaGetSymbolAddress((void**)&wvl, g_wvl);
    cudaGetSymbolAddress((void**)&woh, g_woh); cudaGetSymbolAddress((void**)&wol, g_wol);
    cudaGetSymbolAddress((void**)&f1h, g_f1h); cudaGetSymbolAddress((void**)&f1l, g_f1l);
    cudaGetSymbolAddress((void**)&f2h, g_f2h); cudaGetSymbolAddress((void**)&f2l, g_f2l);

    // 0) split all six weights to bf16 hi/lo in one launch
    split6<<<1152, 256>>>(W_q, W_k, W_v, W_o, fc1_w, fc2_w,
                          wqh, wql, wkh, wkl, wvh, wvl,
                          woh, wol, f1h, f1l, f2h, f2l);

    // 1) LN -> bf16 hi/lo
    ln_kernel<<<MM/8, 256>>>(x, ln_attn_g, ln_attn_b, h1h, h1l);

    // 2) fused QKV projection (pipelined tensor core, fused RoPE/scale/split)
    const float qscale = 0.08838834764831845f;  // 1/sqrt(128)
    cudaFuncSetAttribute(qkv_mm, cudaFuncAttributeMaxDynamicSharedMemorySize, MM3_SMEM);
    qkv_mm<<<dim3(48, MM/128), 256, MM3_SMEM>>>(qscale);

    // 3) causal flash attention (2 CTAs/SM, Qlo in smem, descending work order)
    cudaFuncSetAttribute(fa_mma, cudaFuncAttributeMaxDynamicSharedMemorySize, FA_SMEM);
    fa_mma<<<1024, 128, FA_SMEM>>>(qhi, qlo, khi, klo, vhi, vlo, aoh, aol);

    // 4) O-projection split-K (4 x 512, pipelined) -> FUSED reduce+residual+LN
    cudaFuncSetAttribute(mm3<6,true,true>,  cudaFuncAttributeMaxDynamicSharedMemorySize, MM3_SMEM);
    cudaFuncSetAttribute(mm3<6,false,true>, cudaFuncAttributeMaxDynamicSharedMemorySize, MM3_SMEM);
    cudaFuncSetAttribute(mm3<4,false,true>, cudaFuncAttributeMaxDynamicSharedMemorySize, MM3_SMEM);
    mm3<6,true,true><<<dim3(4, MM/64), 256, MM3_SMEM>>>(aoh, aol, woh, wol, nullptr, nullptr, part, nullptr, nullptr, MM, EE, HD, 512, 1.0f);
    reduce_ln<<<MM/8, 256>>>(part, x, ln_mlp_g, ln_mlp_b, x2, h2h, h2l);

    // 5) MLP: fc1 (pipelined, HALFM, fused bias+GELU+split), fc2 split-K 4x128
    mm3<4,false,true><<<dim3(DHH/128, MM/64), 256, MM3_SMEM>>>(h2h, h2l, f1h, f1l, fc1_b, nullptr, nullptr, th, tl, MM, DHH, EE, EE, 1.0f);
    mm3<6,false,true><<<dim3(4, MM/64), 256, MM3_SMEM>>>(th, tl, f2h, f2l, nullptr, nullptr, part, nullptr, nullptr, MM, EE, DHH, 128, 1.0f);
    reduce_k<4,true><<<(MM*EE)/1024, 256>>>(part, x2, fc2_b, out);
}

// round 16
// speedup vs baseline: 1.0791x; 1.0770x over previous
#include <cuda_runtime.h>
#include <cuda_bf16.h>
#include <cuda_fp16.h>
#include <math.h>
#include <stdint.h>

#define BB 2
#define SS 2048
#define EE 128
#define HH 16
#define DD 128
#define DHH 512
#define MM (BB*SS)     // 4096 rows
#define HD (HH*DD)     // 2048

// ---------------- scratch (static __device__, no allocation) ----------------
__device__ float g_x2[MM*EE];
__device__ float g_part[4*MM*EE];
__device__ __nv_bfloat16 g_h1h[MM*EE],  g_h1l[MM*EE];
__device__ __nv_bfloat16 g_h2h[MM*EE],  g_h2l[MM*EE];
__device__ __nv_bfloat16 g_th [MM*DHH], g_tl [MM*DHH];
__device__ __nv_bfloat16 g_aoh[MM*HD],  g_aol[MM*HD];
__device__ __nv_bfloat16 g_qhi[MM*HD],  g_qlo[MM*HD];
__device__ __nv_bfloat16 g_khi[MM*HD],  g_klo[MM*HD];
__device__ __nv_bfloat16 g_vhi[MM*HD],  g_vlo[MM*HD];   // fp16 bit patterns for V
__device__ __nv_bfloat16 g_wqh[EE*HD],  g_wql[EE*HD];
__device__ __nv_bfloat16 g_wkh[EE*HD],  g_wkl[EE*HD];
__device__ __nv_bfloat16 g_wvh[EE*HD],  g_wvl[EE*HD];
__device__ __nv_bfloat16 g_woh[HD*EE],  g_wol[HD*EE];
__device__ __nv_bfloat16 g_f1h[EE*DHH], g_f1l[EE*DHH];
__device__ __nv_bfloat16 g_f2h[DHH*EE], g_f2l[DHH*EE];

// ======================= warp MMA helpers (baseline PTX) =====================
__device__ __forceinline__ uint32_t smem_u32(const void* p) {
    uint32_t a;
    asm("{ .reg .u64 t; cvta.to.shared.u64 t, %1; cvt.u32.u64 %0, t; }"
        : "=r"(a) : "l"(p));
    return a;
}
__device__ __forceinline__ void mma16816(float* c, const uint32_t* a, const uint32_t* b) {
    asm volatile(
        "mma.sync.aligned.m16n8k16.row.col.f32.bf16.bf16.f32 "
        "{%0,%1,%2,%3}, {%4,%5,%6,%7}, {%8,%9}, {%0,%1,%2,%3};"
        : "+f"(c[0]), "+f"(c[1]), "+f"(c[2]), "+f"(c[3])
        : "r"(a[0]), "r"(a[1]), "r"(a[2]), "r"(a[3]), "r"(b[0]), "r"(b[1]));
}
__device__ __forceinline__ void mma16816h(float* c, const uint32_t* a, const uint32_t* b) {
    asm volatile(
        "mma.sync.aligned.m16n8k16.row.col.f32.f16.f16.f32 "
        "{%0,%1,%2,%3}, {%4,%5,%6,%7}, {%8,%9}, {%0,%1,%2,%3};"
        : "+f"(c[0]), "+f"(c[1]), "+f"(c[2]), "+f"(c[3])
        : "r"(a[0]), "r"(a[1]), "r"(a[2]), "r"(a[3]), "r"(b[0]), "r"(b[1]));
}
__device__ __forceinline__ void ldsm_x4(uint32_t* r, uint32_t addr) {
    asm volatile("ldmatrix.sync.aligned.m8n8.x4.shared.b16 {%0,%1,%2,%3}, [%4];"
        : "=r"(r[0]), "=r"(r[1]), "=r"(r[2]), "=r"(r[3]) : "r"(addr));
}
__device__ __forceinline__ void ldsm_x4_t(uint32_t* r, uint32_t addr) {
    asm volatile("ldmatrix.sync.aligned.m8n8.x4.trans.shared.b16 {%0,%1,%2,%3}, [%4];"
        : "=r"(r[0]), "=r"(r[1]), "=r"(r[2]), "=r"(r[3]) : "r"(addr));
}
__device__ __forceinline__ uint32_t pack_bf2(float a, float b) {
    __nv_bfloat162 h = __halves2bfloat162(__float2bfloat16(a), __float2bfloat16(b));
    return *(uint32_t*)&h;
}
__device__ __forceinline__ uint32_t pack_hf2(float a, float b) {
    __half2 h = __halves2half2(__float2half(a), __float2half(b));
    return *(uint32_t*)&h;
}
__device__ __forceinline__ void cp16(uint32_t smem_addr, const void* gptr) {
    asm volatile("cp.async.cg.shared.global [%0], [%1], 16;"
        :: "r"(smem_addr), "l"(gptr) : "memory");
}
#define CP_COMMIT() asm volatile("cp.async.commit_group;" ::: "memory")
#define CP_WAIT(n)  asm volatile("cp.async.wait_group %0;" :: "n"(n) : "memory")

// 256B-row swizzle (B tiles, FA tiles); 128B-row swizzle (A tiles)
__device__ __forceinline__ uint32_t boff(int r, int cbyte) {
    return (uint32_t)(r * 256 + (cbyte ^ ((r & 7) << 4)));
}
__device__ __forceinline__ uint32_t aoff(int r, int cbyte) {
    return (uint32_t)(r * 128 + (cbyte ^ ((r & 7) << 4)));
}

// ---------------- fp32 -> bf16 hi/lo split: all six weights in ONE launch ----
__global__ void split6(const float* __restrict__ a0, const float* __restrict__ a1,
                       const float* __restrict__ a2, const float* __restrict__ a3,
                       const float* __restrict__ a4, const float* __restrict__ a5,
                       __nv_bfloat16* h0, __nv_bfloat16* l0,
                       __nv_bfloat16* h1, __nv_bfloat16* l1,
                       __nv_bfloat16* h2, __nv_bfloat16* l2,
                       __nv_bfloat16* h3, __nv_bfloat16* l3,
                       __nv_bfloat16* h4, __nv_bfloat16* l4,
                       __nv_bfloat16* h5, __nv_bfloat16* l5) {
    const float* ws[6] = {a0, a1, a2, a3, a4, a5};
    __nv_bfloat16* hs[6] = {h0, h1, h2, h3, h4, h5};
    __nv_bfloat16* ls[6] = {l0, l1, l2, l3, l4, l5};
    int b = blockIdx.x, wi, off;
    if (b < 1024) { wi = b >> 8;       off = (b & 255) * 1024; }
    else          { b -= 1024; wi = 4 + (b >> 6); off = (b & 63) * 1024; }
    int i = off + threadIdx.x * 4;
    float4 v = *(const float4*)(ws[wi] + i);
    __nv_bfloat16 b0 = __float2bfloat16(v.x), b1 = __float2bfloat16(v.y);
    __nv_bfloat16 b2 = __float2bfloat16(v.z), b3 = __float2bfloat16(v.w);
    __nv_bfloat162 hh01 = __halves2bfloat162(b0, b1), hh23 = __halves2bfloat162(b2, b3);
    *(uint2*)(hs[wi] + i) = make_uint2(*(uint32_t*)&hh01, *(uint32_t*)&hh23);
    uint32_t l01 = pack_bf2(v.x - __bfloat162float(b0), v.y - __bfloat162float(b1));
    uint32_t l23 = pack_bf2(v.z - __bfloat162float(b2), v.w - __bfloat162float(b3));
    *(uint2*)(ls[wi] + i) = make_uint2(l01, l23);
}

// ---------------- split-K reduce: out = resid (+bias) + sum partials --------
template<int NS, bool BIAS>
__global__ void reduce_k(const float* __restrict__ part, const float* __restrict__ resid,
                         const float* __restrict__ bias, float* __restrict__ out) {
    int i = (blockIdx.x * 256 + threadIdx.x) * 4;
    float4 acc = *(const float4*)(resid + i);
    if (BIAS) {
        float4 bv = *(const float4*)(bias + (i & (EE - 1)));
        acc.x += bv.x; acc.y += bv.y; acc.z += bv.z; acc.w += bv.w;
    }
    #pragma unroll
    for (int z = 0; z < NS; z++) {
        float4 p = *(const float4*)(part + (size_t)z * (MM * EE) + i);
        acc.x += p.x; acc.y += p.y; acc.z += p.z; acc.w += p.w;
    }
    *(float4*)(out + i) = acc;
}

// ---------------- LayerNorm: one warp per row, bf16 hi/lo out ---------------
__global__ void ln_kernel(const float* __restrict__ x, const float* __restrict__ g,
                          const float* __restrict__ b,
                          __nv_bfloat16* __restrict__ ohi, __nv_bfloat16* __restrict__ olo) {
    int warp = threadIdx.x >> 5, lane = threadIdx.x & 31;
    int row = blockIdx.x * 8 + warp;
    float4 v = ((const float4*)(x + (size_t)row * EE))[lane];
    float s = v.x + v.y + v.z + v.w;
    #pragma unroll
    for (int o = 16; o; o >>= 1) s += __shfl_xor_sync(0xffffffffu, s, o);
    float mu = s * (1.0f / EE);
    float d0 = v.x - mu, d1 = v.y - mu, d2 = v.z - mu, d3 = v.w - mu;
    float q = d0*d0 + d1*d1 + d2*d2 + d3*d3;
    #pragma unroll
    for (int o = 16; o; o >>= 1) q += __shfl_xor_sync(0xffffffffu, q, o);
    float inv = rsqrtf(q * (1.0f / EE) + 1e-5f);
    float4 gg = ((const float4*)g)[lane];
    float4 bb = ((const float4*)b)[lane];
    float r0 = d0 * inv * gg.x + bb.x;
    float r1 = d1 * inv * gg.y + bb.y;
    float r2 = d2 * inv * gg.z + bb.z;
    float r3 = d3 * inv * gg.w + bb.w;
    __nv_bfloat16 h0 = __float2bfloat16(r0), h1 = __float2bfloat16(r1);
    __nv_bfloat16 h2 = __float2bfloat16(r2), h3 = __float2bfloat16(r3);
    __nv_bfloat162 hh01 = __halves2bfloat162(h0, h1), hh23 = __halves2bfloat162(h2, h3);
    size_t base = (size_t)row * EE + lane * 4;
    *(uint2*)(ohi + base) = make_uint2(*(uint32_t*)&hh01, *(uint32_t*)&hh23);
    uint32_t l01 = pack_bf2(r0 - __bfloat162float(h0), r1 - __bfloat162float(h1));
    uint32_t l23 = pack_bf2(r2 - __bfloat162float(h2), r3 - __bfloat162float(h3));
    *(uint2*)(olo + base) = make_uint2(l01, l23);
}

// ---- fused split-K reduce + LayerNorm (O-proj epilogue + LN2 in one pass) --
__global__ void reduce_ln(const float* __restrict__ part, const float* __restrict__ resid,
                          const float* __restrict__ g, const float* __restrict__ b,
                          float* __restrict__ x2out,
                          __nv_bfloat16* __restrict__ ohi, __nv_bfloat16* __restrict__ olo) {
    int warp = threadIdx.x >> 5, lane = threadIdx.x & 31;
    int row = blockIdx.x * 8 + warp;
    size_t i = (size_t)row * EE + lane * 4;
    float4 v = *(const float4*)(resid + i);
    #pragma unroll
    for (int z = 0; z < 4; z++) {
        float4 p = *(const float4*)(part + (size_t)z * (MM * EE) + i);
        v.x += p.x; v.y += p.y; v.z += p.z; v.w += p.w;
    }
    *(float4*)(x2out + i) = v;
    float s = v.x + v.y + v.z + v.w;
    #pragma unroll
    for (int o = 16; o; o >>= 1) s += __shfl_xor_sync(0xffffffffu, s, o);
    float mu = s * (1.0f / EE);
    float d0 = v.x - mu, d1 = v.y - mu, d2 = v.z - mu, d3 = v.w - mu;
    float q = d0*d0 + d1*d1 + d2*d2 + d3*d3;
    #pragma unroll
    for (int o = 16; o; o >>= 1) q += __shfl_xor_sync(0xffffffffu, q, o);
    float inv = rsqrtf(q * (1.0f / EE) + 1e-5f);
    float4 gg = ((const float4*)g)[lane];
    float4 bb = ((const float4*)b)[lane];
    float r0 = d0 * inv * gg.x + bb.x;
    float r1 = d1 * inv * gg.y + bb.y;
    float r2 = d2 * inv * gg.z + bb.z;
    float r3 = d3 * inv * gg.w + bb.w;
    __nv_bfloat16 h0 = __float2bfloat16(r0), h1 = __float2bfloat16(r1);
    __nv_bfloat16 h2 = __float2bfloat16(r2), h3 = __float2bfloat16(r3);
    __nv_bfloat162 hh01 = __halves2bfloat162(h0, h1), hh23 = __halves2bfloat162(h2, h3);
    *(uint2*)(ohi + i) = make_uint2(*(uint32_t*)&hh01, *(uint32_t*)&hh23);
    uint32_t l01 = pack_bf2(r0 - __bfloat162float(h0), r1 - __bfloat162float(h1));
    uint32_t l23 = pack_bf2(r2 - __bfloat162float(h2), r3 - __bfloat162float(h3));
    *(uint2*)(olo + i) = make_uint2(l01, l23);
}

// =============== shared smem layout for projection GEMMs (2 stages) =========
#define MM3_AHI 0u
#define MM3_ALO 16384u
#define MM3_BHI 32768u
#define MM3_BLO 49152u
#define MM3_STAGE 65536u
#define MM3_SMEM 131072

// =============== fused QKV projection (pipelined, bf16x3) ===================
// V (mi==2) output is emitted as fp16 hi/lo (for 2-term fp16 PV in fa_mma).
__global__ __launch_bounds__(256, 1)
void qkv_mm(float qscale)
{
    extern __shared__ char sm[];
    uint32_t sb = smem_u32(sm);
    const int tid = threadIdx.x;
    const int w = tid >> 5, ln = tid & 31;
    const int tig = ln & 3, gid = ln >> 2;
    const int mi = blockIdx.x >> 4;
    const int n0 = (blockIdx.x & 15) * 128;
    const int m0 = blockIdx.y * 128;
    const __nv_bfloat16* Bh_ = (mi == 0) ? g_wqh : (mi == 1) ? g_wkh : g_wvh;
    const __nv_bfloat16* Bl_ = (mi == 0) ? g_wql : (mi == 1) ? g_wkl : g_wvl;
    __nv_bfloat16* Oh_ = (mi == 0) ? g_qhi : (mi == 1) ? g_khi : g_vhi;
    __nv_bfloat16* Ol_ = (mi == 0) ? g_qlo : (mi == 1) ? g_klo : g_vlo;
    const float scale = (mi == 0) ? qscale : 1.0f;

    float C[16][4];
    #pragma unroll
    for (int j = 0; j < 16; j++)
        #pragma unroll
        for (int e = 0; e < 4; e++) C[j][e] = 0.f;

    const int arow = 16 * w + ((ln >> 3) & 1) * 8 + (ln & 7);
    const int akb  = (ln >> 4) * 16;
    const int brow = ((ln >> 3) & 1) * 8 + (ln & 7);
    const int bcb  = (ln >> 4) << 4;

    // prologue: prefetch k-iter 0 into stage 0
    for (int f = tid; f < 1024; f += 256) {
        int r = f >> 3, seg = f & 7;
        size_t g = (size_t)(m0 + r) * EE + seg * 8;
        uint32_t so = aoff(r, seg * 16);
        cp16(sb + MM3_AHI + so, g_h1h + g);
        cp16(sb + MM3_ALO + so, g_h1l + g);
    }
    for (int f = tid; f < 1024; f += 256) {
        int r = f >> 4, seg = f & 15;
        size_t g = (size_t)r * HD + n0 + seg * 8;
        uint32_t so = boff(r, seg * 16);
        cp16(sb + MM3_BHI + so, Bh_ + g);
        cp16(sb + MM3_BLO + so, Bl_ + g);
    }
    CP_COMMIT();

    #pragma unroll
    for (int it = 0; it < 2; it++) {
        uint32_t st = (uint32_t)(it & 1) * MM3_STAGE;
        __syncthreads();
        if (it == 0) {
            for (int f = tid; f < 1024; f += 256) {
                int r = f >> 3, seg = f & 7;
                size_t g = (size_t)(m0 + r) * EE + 64 + seg * 8;
                uint32_t so = aoff(r, seg * 16);
                cp16(sb + MM3_STAGE + MM3_AHI + so, g_h1h + g);
                cp16(sb + MM3_STAGE + MM3_ALO + so, g_h1l + g);
            }
            for (int f = tid; f < 1024; f += 256) {
                int r = f >> 4, seg = f & 15;
                size_t g = (size_t)(64 + r) * HD + n0 + seg * 8;
                uint32_t so = boff(r, seg * 16);
                cp16(sb + MM3_STAGE + MM3_BHI + so, Bh_ + g);
                cp16(sb + MM3_STAGE + MM3_BLO + so, Bl_ + g);
            }
            CP_COMMIT();
            CP_WAIT(1);
        } else {
            CP_WAIT(0);
        }
        __syncthreads();

        uint32_t Ah[4][4], Al[4][4];
        #pragma unroll
        for (int kk = 0; kk < 4; kk++) {
            uint32_t off = aoff(arow, kk * 32 + akb);
            ldsm_x4(Ah[kk], sb + st + MM3_AHI + off);
            ldsm_x4(Al[kk], sb + st + MM3_ALO + off);
        }
        #pragma unroll
        for (int jp = 0; jp < 8; jp++) {
            int ncb = 32 * jp;
            #pragma unroll
            for (int kk = 0; kk < 4; kk++) {
                uint32_t off = boff(16 * kk + brow, ncb + bcb);
                uint32_t Bh[4], Bl[4];
                ldsm_x4_t(Bh, sb + st + MM3_BHI + off);
                mma16816(C[2*jp],   Ah[kk], Bh);
                mma16816(C[2*jp+1], Ah[kk], Bh + 2);
                mma16816(C[2*jp],   Al[kk], Bh);
                mma16816(C[2*jp+1], Al[kk], Bh + 2);
                ldsm_x4_t(Bl, sb + st + MM3_BLO + off);
                mma16816(C[2*jp],   Ah[kk], Bl);
                mma16816(C[2*jp+1], Ah[kk], Bl + 2);
            }
        }
    }

    // epilogue: scale, RoPE (Q/K), hi/lo split to (B,H,S,D)
    const int r0 = m0 + 16 * w + gid;
    const int r1 = r0 + 8;
    int b_ = r0 >> 11, s0 = r0 & 2047, s1 = r1 & 2047;
    #pragma unroll
    for (int j = 0; j < 16; j++) {
        int colg = n0 + 8 * j + 2 * tig;
        int h = colg >> 7, d = colg & 127;
        float o00 = C[j][0] * scale, o01 = C[j][1] * scale;
        float o10 = C[j][2] * scale, o11 = C[j][3] * scale;
        if (mi < 2) {
            int t2 = d >> 1;
            float f = expf((float)t2 * -0.14391157f);
            float si0, co0, si1, co1;
            sincosf((float)s0 * f, &si0, &co0);
            sincosf((float)s1 * f, &si1, &co1);
            float a = o00 * co0 - o01 * si0, b2 = o00 * si0 + o01 * co0;
            o00 = a; o01 = b2;
            a = o10 * co1 - o11 * si1; b2 = o10 * si1 + o11 * co1;
            o10 = a; o11 = b2;
        }
        size_t oi0 = (((size_t)(b_ * HH + h) * SS + s0) * DD + d);
        size_t oi1 = (((size_t)(b_ * HH + h) * SS + s1) * DD + d);
        if (mi < 2) {
            __nv_bfloat16 h00 = __float2bfloat16(o00), h01 = __float2bfloat16(o01);
            __nv_bfloat16 h10 = __float2bfloat16(o10), h11 = __float2bfloat16(o11);
            __nv_bfloat162 p0 = __halves2bfloat162(h00, h01);
            __nv_bfloat162 p1 = __halves2bfloat162(h10, h11);
            *(uint32_t*)(Oh_ + oi0) = *(uint32_t*)&p0;
            *(uint32_t*)(Oh_ + oi1) = *(uint32_t*)&p1;
            *(uint32_t*)(Ol_ + oi0) = pack_bf2(o00 - __bfloat162float(h00), o01 - __bfloat162float(h01));
            *(uint32_t*)(Ol_ + oi1) = pack_bf2(o10 - __bfloat162float(h10), o11 - __bfloat162float(h11));
        } else {
            __half h00 = __float2half(o00), h01 = __float2half(o01);
            __half h10 = __float2half(o10), h11 = __float2half(o11);
            __half2 p0 = __halves2half2(h00, h01);
            __half2 p1 = __halves2half2(h10, h11);
            *(uint32_t*)(Oh_ + oi0) = *(uint32_t*)&p0;
            *(uint32_t*)(Oh_ + oi1) = *(uint32_t*)&p1;
            *(uint32_t*)(Ol_ + oi0) = pack_hf2(o00 - __half2float(h00), o01 - __half2float(h01));
            *(uint32_t*)(Ol_ + oi1) = pack_hf2(o10 - __half2float(h10), o11 - __half2float(h11));
        }
    }
}

// =============== bf16x3 tensor-core GEMM (pipelined) ========================
// MODE 4: gelu(acc + bias) -> bf16 hi/lo               (fc1)
// MODE 6: split-K partial: fp32 to out + blockIdx.x*M*N, k in [bx*kspl, +kspl)
template<int MODE, bool AG, bool HALFM>
__global__ __launch_bounds__(256)
void mm3(const __nv_bfloat16* __restrict__ Ahi, const __nv_bfloat16* __restrict__ Alo,
         const __nv_bfloat16* __restrict__ Bhi, const __nv_bfloat16* __restrict__ Blo,
         const float* __restrict__ bias, const float* __restrict__ resid,
         float* __restrict__ out,
         __nv_bfloat16* __restrict__ ohi, __nv_bfloat16* __restrict__ olo,
         int M, int N, int K, int kspl, float qscale)
{
    extern __shared__ char sm[];
    uint32_t sb = smem_u32(sm);
    constexpr int MT = HALFM ? 64 : 128;
    constexpr int NJ = HALFM ? 8 : 16;
    const int tid = threadIdx.x;
    const int w = tid >> 5, ln = tid & 31;
    const int tig = ln & 3, gid = ln >> 2;
    const int wr = HALFM ? (w & 3) : w;
    const int wc = HALFM ? (w >> 2) * 64 : 0;
    const int m0 = blockIdx.y * MT;
    const int n0 = (MODE == 6) ? 0 : blockIdx.x * 128;
    const int kb = (MODE == 6) ? blockIdx.x * kspl : 0;
    const int ke = (MODE == 6) ? kb + kspl : K;
    const int niter = (ke - kb) >> 6;

    float C[NJ][4];
    #pragma unroll
    for (int j = 0; j < NJ; j++)
        #pragma unroll
        for (int e = 0; e < 4; e++) C[j][e] = 0.f;

    const int arow = 16 * wr + ((ln >> 3) & 1) * 8 + (ln & 7);
    const int akb  = (ln >> 4) * 16;
    const int brow = ((ln >> 3) & 1) * 8 + (ln & 7);
    const int bcb  = (ln >> 4) << 4;

    // prologue: prefetch iter 0
    {
        int k0 = kb;
        for (int f = tid; f < MT * 8; f += 256) {
            int r = f >> 3, seg = f & 7;
            size_t g;
            if (!AG) {
                g = (size_t)(m0 + r) * K + k0 + seg * 8;
            } else {
                int rr = m0 + r;
                int b_ = rr >> 11, s_ = rr & 2047;
                int kk = k0 + seg * 8;
                g = ((size_t)(b_ * HH + (kk >> 7)) * SS + s_) * DD + (kk & 127);
            }
            uint32_t so = aoff(r, seg * 16);
            cp16(sb + MM3_AHI + so, Ahi + g);
            cp16(sb + MM3_ALO + so, Alo + g);
        }
        for (int f = tid; f < 1024; f += 256) {
            int r = f >> 4, seg = f & 15;
            size_t g = (size_t)(k0 + r) * N + n0 + seg * 8;
            uint32_t so = boff(r, seg * 16);
            cp16(sb + MM3_BHI + so, Bhi + g);
            cp16(sb + MM3_BLO + so, Blo + g);
        }
        CP_COMMIT();
    }

    for (int it = 0; it < niter; it++) {
        uint32_t st = (uint32_t)(it & 1) * MM3_STAGE;
        __syncthreads();
        if (it + 1 < niter) {
            int k0 = kb + (it + 1) * 64;
            uint32_t stn = (uint32_t)((it + 1) & 1) * MM3_STAGE;
            for (int f = tid; f < MT * 8; f += 256) {
                int r = f >> 3, seg = f & 7;
                size_t g;
                if (!AG) {
                    g = (size_t)(m0 + r) * K + k0 + seg * 8;
                } else {
                    int rr = m0 + r;
                    int b_ = rr >> 11, s_ = rr & 2047;
                    int kk = k0 + seg * 8;
                    g = ((size_t)(b_ * HH + (kk >> 7)) * SS + s_) * DD + (kk & 127);
                }
                uint32_t so = aoff(r, seg * 16);
                cp16(sb + stn + MM3_AHI + so, Ahi + g);
                cp16(sb + stn + MM3_ALO + so, Alo + g);
            }
            for (int f = tid; f < 1024; f += 256) {
                int r = f >> 4, seg = f & 15;
                size_t g = (size_t)(k0 + r) * N + n0 + seg * 8;
                uint32_t so = boff(r, seg * 16);
                cp16(sb + stn + MM3_BHI + so, Bhi + g);
                cp16(sb + stn + MM3_BLO + so, Blo + g);
            }
            CP_COMMIT();
            CP_WAIT(1);
        } else {
            CP_WAIT(0);
        }
        __syncthreads();

        uint32_t Ah[4][4], Al[4][4];
        #pragma unroll
        for (int kk = 0; kk < 4; kk++) {
            uint32_t off = aoff(arow, kk * 32 + akb);
            ldsm_x4(Ah[kk], sb + st + MM3_AHI + off);
            ldsm_x4(Al[kk], sb + st + MM3_ALO + off);
        }
        #pragma unroll
        for (int jp = 0; jp < NJ / 2; jp++) {
            int ncb = (wc + 16 * jp) * 2;
            #pragma unroll
            for (int kk = 0; kk < 4; kk++) {
                uint32_t off = boff(16 * kk + brow, ncb + bcb);
                uint32_t Bh[4], Bl[4];
                ldsm_x4_t(Bh, sb + st + MM3_BHI + off);
                mma16816(C[2*jp],   Ah[kk], Bh);
                mma16816(C[2*jp+1], Ah[kk], Bh + 2);
                mma16816(C[2*jp],   Al[kk], Bh);
                mma16816(C[2*jp+1], Al[kk], Bh + 2);
                ldsm_x4_t(Bl, sb + st + MM3_BLO + off);
                mma16816(C[2*jp],   Ah[kk], Bl);
                mma16816(C[2*jp+1], Ah[kk], Bl + 2);
            }
        }
    }

    const int r0 = m0 + 16 * wr + gid;
    const int r1 = r0 + 8;
    if (MODE == 6) {
        float* po = out + (size_t)blockIdx.x * M * N;
        #pragma unroll
        for (int j = 0; j < NJ; j++) {
            int colg = wc + 8 * j + 2 * tig;
            size_t i0 = (size_t)r0 * N + colg;
            size_t i1 = (size_t)r1 * N + colg;
            *(float2*)(po + i0) = make_float2(C[j][0], C[j][1]);
            *(float2*)(po + i1) = make_float2(C[j][2], C[j][3]);
        }
    } else if (MODE == 4) {
        #pragma unroll
        for (int j = 0; j < NJ; j++) {
            int colg = n0 + wc + 8 * j + 2 * tig;
            size_t i0 = (size_t)r0 * N + colg;
            size_t i1 = (size_t)r1 * N + colg;
            float v00 = C[j][0], v01 = C[j][1], v10 = C[j][2], v11 = C[j][3];
            float b0 = bias[colg], b1 = bias[colg + 1];
            v00 += b0; v01 += b1; v10 += b0; v11 += b1;
            v00 = 0.5f * v00 * (1.0f + erff(v00 * 0.70710678f));
            v01 = 0.5f * v01 * (1.0f + erff(v01 * 0.70710678f));
            v10 = 0.5f * v10 * (1.0f + erff(v10 * 0.70710678f));
            v11 = 0.5f * v11 * (1.0f + erff(v11 * 0.70710678f));
            __nv_bfloat16 h00 = __float2bfloat16(v00), h01 = __float2bfloat16(v01);
            __nv_bfloat16 h10 = __float2bfloat16(v10), h11 = __float2bfloat16(v11);
            __nv_bfloat162 p0 = __halves2bfloat162(h00, h01);
            __nv_bfloat162 p1 = __halves2bfloat162(h10, h11);
            *(uint32_t*)(ohi + i0) = *(uint32_t*)&p0;
            *(uint32_t*)(ohi + i1) = *(uint32_t*)&p1;
            *(uint32_t*)(olo + i0) = pack_bf2(v00 - __bfloat162float(h00), v01 - __bfloat162float(h01));
            *(uint32_t*)(olo + i1) = pack_bf2(v10 - __bfloat162float(h10), v11 - __bfloat162float(h11));
        }
    }
}

// ============== mma.sync flash attention (bf16x3 S, fp16x2 PV, 2 CTAs/SM) ===
// CTA: 128 threads, 64 query rows. Grid 1024 (globally-descending work).
// Smem/CTA = 112KB: K [0,32K), V double [32K,96K), Qlo resident [96K,112K).
// P stored as single fp16 (2^-11 rounding); V fp16 hi/lo -> 2-term PV.
#define FA_KHI 0u
#define FA_KLO 16384u
#define FA_V0  32768u
#define FA_VST 32768u
#define FA_QLO 98304u
#define FA_SMEM 114688

__device__ __forceinline__ uint32_t fa_off(int r, int cbyte) {
    return (uint32_t)(r * 256 + (cbyte ^ ((r & 7) << 4)));
}

__global__ __launch_bounds__(128, 2)
void fa_mma(const __nv_bfloat16* __restrict__ qhi, const __nv_bfloat16* __restrict__ qlo,
            const __nv_bfloat16* __restrict__ khi, const __nv_bfloat16* __restrict__ klo,
            const __nv_bfloat16* __restrict__ vhi, const __nv_bfloat16* __restrict__ vlo,
            __nv_bfloat16* __restrict__ Ohi, __nv_bfloat16* __restrict__ Olo)
{
    extern __shared__ char sm[];
    uint32_t sb = smem_u32(sm);
    const int tid = threadIdx.x;
    const int w = tid >> 5, ln = tid & 31;
    const int tig = ln & 3, gid = ln >> 2;
    const int bid = blockIdx.x;
    const int m0 = (31 - (bid >> 5)) * 64;    // globally descending work
    const int bh = bid & 31;
    const size_t base = (size_t)bh * SS * DD;

    // ---- stage Q: hi via K region (transient), lo into resident FA_QLO ----
    for (int f = tid; f < 1024; f += 128) {
        int r = f >> 4, c16 = f & 15;
        size_t g = base + (size_t)(m0 + r) * DD + c16 * 8;
        uint32_t so = fa_off(r, c16 * 16);
        *(uint4*)(sm + FA_KHI + so) = *(const uint4*)(qhi + g);
        *(uint4*)(sm + FA_QLO + so) = *(const uint4*)(qlo + g);
    }
    __syncthreads();
    const int qrow = 16 * w + ((ln >> 3) & 1) * 8 + (ln & 7);
    const int qkb  = (ln >> 4) * 16;
    uint32_t Qh[8][4];
    #pragma unroll
    for (int kk = 0; kk < 8; kk++)
        ldsm_x4(Qh[kk], sb + FA_KHI + fa_off(qrow, kk * 32 + qkb));
    __syncthreads();

    float Oa[16][4];
    #pragma unroll
    for (int j = 0; j < 16; j++)
        #pragma unroll
        for (int e = 0; e < 4; e++) Oa[j][e] = 0.f;
    float m0r = -1e30f, m1r = -1e30f, l0r = 0.f, l1r = 0.f;

    const int grow0 = m0 + 16 * w + gid;
    const int grow1 = grow0 + 8;
    const int nk = m0 / 64 + 1;

    // ---- prologue: K(0), V(0) ----
    for (int f = tid; f < 1024; f += 128) {
        int r = f >> 4, c16 = f & 15;
        size_t g = base + (size_t)r * DD + c16 * 8;
        uint32_t so = fa_off(r, c16 * 16);
        cp16(sb + FA_KHI + so, khi + g);
        cp16(sb + FA_KLO + so, klo + g);
        cp16(sb + FA_V0 + so, vhi + g);
        cp16(sb + FA_V0 + 16384 + so, vlo + g);
    }
    CP_COMMIT();

    for (int t = 0; t < nk; t++) {
        int n0 = t * 64;
        uint32_t vb = FA_V0 + (uint32_t)(t & 1) * FA_VST;
        CP_WAIT(0);        // K(t), V(t) resident
        __syncthreads();

        // ---- S = Q K^T (3-term bf16); kk outer, Ql re-loaded per kk ----
        float S[8][4];
        #pragma unroll
        for (int j = 0; j < 8; j++)
            #pragma unroll
            for (int e = 0; e < 4; e++) S[j][e] = 0.f;
        {
            int brow = ((ln >> 4) << 3) + (ln & 7);
            int bkb  = ((ln >> 3) & 1) << 4;
            #pragma unroll
            for (int kk = 0; kk < 8; kk++) {
                uint32_t Qlt[4];
                ldsm_x4(Qlt, sb + FA_QLO + fa_off(qrow, kk * 32 + qkb));
                #pragma unroll
                for (int jp = 0; jp < 4; jp++) {
                    int r_ = 16 * jp + brow;
                    uint32_t off = fa_off(r_, kk * 32 + bkb);
                    uint32_t Bh[4], Bl[4];
                    ldsm_x4(Bh, sb + FA_KHI + off);
                    mma16816(S[2*jp],   Qh[kk], Bh);
                    mma16816(S[2*jp+1], Qh[kk], Bh + 2);
                    mma16816(S[2*jp],   Qlt, Bh);
                    mma16816(S[2*jp+1], Qlt, Bh + 2);
                    ldsm_x4(Bl, sb + FA_KLO + off);
                    mma16816(S[2*jp],   Qh[kk], Bl);
                    mma16816(S[2*jp+1], Qh[kk], Bl + 2);
                }
            }
        }
        __syncthreads();   // all warps done reading K(t)

        // ---- prefetch K(t+1) and V(t+1) (overlaps softmax + PV below) ----
        if (t + 1 < nk) {
            int n1 = n0 + 64;
            uint32_t vbn = FA_V0 + (uint32_t)((t + 1) & 1) * FA_VST;
            for (int f = tid; f < 1024; f += 128) {
                int r = f >> 4, c16 = f & 15;
                size_t g = base + (size_t)(n1 + r) * DD + c16 * 8;
                uint32_t so = fa_off(r, c16 * 16);
                cp16(sb + FA_KHI + so, khi + g);
                cp16(sb + FA_KLO + so, klo + g);
                cp16(sb + vbn + so, vhi + g);
                cp16(sb + vbn + 16384 + so, vlo + g);
            }
            CP_COMMIT();
        }

        // ---- causal mask (diagonal tile only) ----
        if (n0 + 63 > m0 + 16 * w) {
            #pragma unroll
            for (int j = 0; j < 8; j++) {
                int c = n0 + 8 * j + 2 * tig;
                if (c     > grow0) S[j][0] = -1e30f;
                if (c + 1 > grow0) S[j][1] = -1e30f;
                if (c     > grow1) S[j][2] = -1e30f;
                if (c + 1 > grow1) S[j][3] = -1e30f;
            }
        }

        // ---- online softmax (P packed as single fp16) ----
        float mx0 = -1e30f, mx1 = -1e30f;
        #pragma unroll
        for (int j = 0; j < 8; j++) {
            mx0 = fmaxf(mx0, fmaxf(S[j][0], S[j][1]));
            mx1 = fmaxf(mx1, fmaxf(S[j][2], S[j][3]));
        }
        mx0 = fmaxf(mx0, __shfl_xor_sync(0xffffffffu, mx0, 1));
        mx0 = fmaxf(mx0, __shfl_xor_sync(0xffffffffu, mx0, 2));
        mx1 = fmaxf(mx1, __shfl_xor_sync(0xffffffffu, mx1, 1));
        mx1 = fmaxf(mx1, __shfl_xor_sync(0xffffffffu, mx1, 2));
        float mn0 = fmaxf(m0r, mx0), mn1 = fmaxf(m1r, mx1);
        bool nochg = (mn0 == m0r) && (mn1 == m1r);
        float a0 = nochg ? 1.f : __expf(m0r - mn0);
        float a1 = nochg ? 1.f : __expf(m1r - mn1);
        m0r = mn0; m1r = mn1;
        l0r *= a0; l1r *= a1;

        uint32_t Ph[4][4];
        float ls0 = 0.f, ls1 = 0.f;
        #pragma unroll
        for (int j = 0; j < 8; j++) {
            float p0 = __expf(S[j][0] - mn0);
            float p1 = __expf(S[j][1] - mn0);
            float p2 = __expf(S[j][2] - mn1);
            float p3 = __expf(S[j][3] - mn1);
            ls0 += p0 + p1; ls1 += p2 + p3;
            int kk = j >> 1, q = (j & 1) * 2;
            Ph[kk][q]     = pack_hf2(p0, p1);
            Ph[kk][q + 1] = pack_hf2(p2, p3);
        }
        l0r += ls0; l1r += ls1;

        if (!__all_sync(0xffffffffu, nochg)) {
            #pragma unroll
            for (int j = 0; j < 16; j++) {
                Oa[j][0] *= a0; Oa[j][1] *= a0;
                Oa[j][2] *= a1; Oa[j][3] *= a1;
            }
        }

        // ---- O += P V (2-term fp16: Ph*Vh + Ph*Vl) ----
        {
            int vrow = ((ln >> 3) & 1) * 8 + (ln & 7);
            int vcb  = (ln >> 4) << 4;
            #pragma unroll
            for (int jp = 0; jp < 8; jp++) {
                #pragma unroll
                for (int kk = 0; kk < 4; kk++) {
                    int r_ = 16 * kk + vrow;
                    uint32_t off = fa_off(r_, 32 * jp + vcb);
                    uint32_t Bh[4], Bl[4];
                    ldsm_x4_t(Bh, sb + vb + off);
                    mma16816h(Oa[2*jp],   Ph[kk], Bh);
                    mma16816h(Oa[2*jp+1], Ph[kk], Bh + 2);
                    ldsm_x4_t(Bl, sb + vb + 16384 + off);
                    mma16816h(Oa[2*jp],   Ph[kk], Bl);
                    mma16816h(Oa[2*jp+1], Ph[kk], Bl + 2);
                }
            }
        }
    }

    // ---- finalize: reduce l, normalize, split hi/lo, store ----
    l0r += __shfl_xor_sync(0xffffffffu, l0r, 1);
    l0r += __shfl_xor_sync(0xffffffffu, l0r, 2);
    l1r += __shfl_xor_sync(0xffffffffu, l1r, 1);
    l1r += __shfl_xor_sync(0xffffffffu, l1r, 2);
    float inv0 = 1.0f / l0r, inv1 = 1.0f / l1r;
    #pragma unroll
    for (int j = 0; j < 16; j++) {
        int col = 8 * j + 2 * tig;
        size_t i0 = base + (size_t)grow0 * DD + col;
        size_t i1 = base + (size_t)grow1 * DD + col;
        float v00 = Oa[j][0] * inv0, v01 = Oa[j][1] * inv0;
        float v10 = Oa[j][2] * inv1, v11 = Oa[j][3] * inv1;
        __nv_bfloat16 h00 = __float2bfloat16(v00), h01 = __float2bfloat16(v01);
        __nv_bfloat16 h10 = __float2bfloat16(v10), h11 = __float2bfloat16(v11);
        __nv_bfloat162 p0 = __halves2bfloat162(h00, h01);
        __nv_bfloat162 p1 = __halves2bfloat162(h10, h11);
        *(uint32_t*)(Ohi + i0) = *(uint32_t*)&p0;
        *(uint32_t*)(Ohi + i1) = *(uint32_t*)&p1;
        *(uint32_t*)(Olo + i0) = pack_bf2(v00 - __bfloat162float(h00), v01 - __bfloat162float(h01));
        *(uint32_t*)(Olo + i1) = pack_bf2(v10 - __bfloat162float(h10), v11 - __bfloat162float(h11));
    }
}

// ---------------- launch -----------------------------------------------------
extern "C" void kernel_launch(void* const* d_in, const int* in_sizes, int n_in,
                              void* d_out, int out_size) {
    const float* x        = (const float*)d_in[0];
    const float* W_q      = (const float*)d_in[1];
    const float* W_k      = (const float*)d_in[2];
    const float* W_v      = (const float*)d_in[3];
    const float* W_o      = (const float*)d_in[4];
    const float* ln_attn_g= (const float*)d_in[5];
    const float* ln_attn_b= (const float*)d_in[6];
    const float* fc1_w    = (const float*)d_in[7];
    const float* fc1_b    = (const float*)d_in[8];
    const float* fc2_w    = (const float*)d_in[9];
    const float* fc2_b    = (const float*)d_in[10];
    const float* ln_mlp_g = (const float*)d_in[11];
    const float* ln_mlp_b = (const float*)d_in[12];
    float* out = (float*)d_out;

    float *x2, *part;
    __nv_bfloat16 *h1h, *h1l, *h2h, *h2l, *th, *tl, *aoh, *aol;
    __nv_bfloat16 *qhi, *qlo, *khi, *klo, *vhi, *vlo;
    __nv_bfloat16 *wqh, *wql, *wkh, *wkl, *wvh, *wvl, *woh, *wol, *f1h, *f1l, *f2h, *f2l;
    cudaGetSymbolAddress((void**)&x2,  g_x2);
    cudaGetSymbolAddress((void**)&part, g_part);
    cudaGetSymbolAddress((void**)&h1h, g_h1h); cudaGetSymbolAddress((void**)&h1l, g_h1l);
    cudaGetSymbolAddress((void**)&h2h, g_h2h); cudaGetSymbolAddress((void**)&h2l, g_h2l);
    cudaGetSymbolAddress((void**)&th,  g_th);  cudaGetSymbolAddress((void**)&tl,  g_tl);
    cudaGetSymbolAddress((void**)&aoh, g_aoh); cudaGetSymbolAddress((void**)&aol, g_aol);
    cudaGetSymbolAddress((void**)&qhi, g_qhi); cudaGetSymbolAddress((void**)&qlo, g_qlo);
    cudaGetSymbolAddress((void**)&khi, g_khi); cudaGetSymbolAddress((void**)&klo, g_klo);
    cudaGetSymbolAddress((void**)&vhi, g_vhi); cudaGetSymbolAddress((void**)&vlo, g_vlo);
    cudaGetSymbolAddress((void**)&wqh, g_wqh); cudaGetSymbolAddress((void**)&wql, g_wql);
    cudaGetSymbolAddress((void**)&wkh, g_wkh); cudaGetSymbolAddress((void**)&wkl, g_wkl);
    cudaGetSymbolAddress((void**)&wvh, g_wvh); cudaGetSymbolAddress((void**)&wvl, g_wvl);
    cudaGetSymbolAddress((void**)&woh, g_woh); cudaGetSymbolAddress((void**)&wol, g_wol);
    cudaGetSymbolAddress((void**)&f1h, g_f1h); cudaGetSymbolAddress((void**)&f1l, g_f1l);
    cudaGetSymbolAddress((void**)&f2h, g_f2h); cudaGetSymbolAddress((void**)&f2l, g_f2l);

    // 0) split all six weights to bf16 hi/lo in one launch
    split6<<<1152, 256>>>(W_q, W_k, W_v, W_o, fc1_w, fc2_w,
                          wqh, wql, wkh, wkl, wvh, wvl,
                          woh, wol, f1h, f1l, f2h, f2l);

    // 1) LN -> bf16 hi/lo
    ln_kernel<<<MM/8, 256>>>(x, ln_attn_g, ln_attn_b, h1h, h1l);

    // 2) fused QKV projection (pipelined; V emitted as fp16 hi/lo)
    const float qscale = 0.08838834764831845f;  // 1/sqrt(128)
    cudaFuncSetAttribute(qkv_mm, cudaFuncAttributeMaxDynamicSharedMemorySize, MM3_SMEM);
    qkv_mm<<<dim3(48, MM/128), 256, MM3_SMEM>>>(qscale);

    // 3) causal flash attention (bf16x3 S, fp16x2 PV, 2 CTAs/SM)
    cudaFuncSetAttribute(fa_mma, cudaFuncAttributeMaxDynamicSharedMemorySize, FA_SMEM);
    fa_mma<<<1024, 128, FA_SMEM>>>(qhi, qlo, khi, klo, vhi, vlo, aoh, aol);

    // 4) O-projection split-K (4 x 512, pipelined) -> FUSED reduce+residual+LN
    cudaFuncSetAttribute(mm3<6,true,true>,  cudaFuncAttributeMaxDynamicSharedMemorySize, MM3_SMEM);
    cudaFuncSetAttribute(mm3<6,false,true>, cudaFuncAttributeMaxDynamicSharedMemorySize, MM3_SMEM);
    cudaFuncSetAttribute(mm3<4,false,true>, cudaFuncAttributeMaxDynamicSharedMemorySize, MM3_SMEM);
    mm3<6,true,true><<<dim3(4, MM/64), 256, MM3_SMEM>>>(aoh, aol, woh, wol, nullptr, nullptr, part, nullptr, nullptr, MM, EE, HD, 512, 1.0f);
    reduce_ln<<<MM/8, 256>>>(part, x, ln_mlp_g, ln_mlp_b, x2, h2h, h2l);

    // 5) MLP: fc1 (pipelined, HALFM, fused bias+GELU+split), fc2 split-K 4x128
    mm3<4,false,true><<<dim3(DHH/128, MM/64), 256, MM3_SMEM>>>(h2h, h2l, f1h, f1l, fc1_b, nullptr, nullptr, th, tl, MM, DHH, EE, EE, 1.0f);
    mm3<6,false,true><<<dim3(4, MM/64), 256, MM3_SMEM>>>(th, tl, f2h, f2l, nullptr, nullptr, part, nullptr, nullptr, MM, EE, DHH, 128, 1.0f);
    reduce_k<4,true><<<(MM*EE)/1024, 256>>>(part, x2, fc2_b, out);
}

// round 17
// speedup vs baseline: 1.1804x; 1.0939x over previous
#include <cuda_runtime.h>
#include <cuda_bf16.h>
#include <cuda_fp16.h>
#include <math.h>
#include <stdint.h>

#define BB 2
#define SS 2048
#define EE 128
#define HH 16
#define DD 128
#define DHH 512
#define MM (BB*SS)     // 4096 rows
#define HD (HH*DD)     // 2048

// ---------------- scratch (static __device__, no allocation) ----------------
__device__ float g_x2[MM*EE];
__device__ float g_part[4*MM*EE];
__device__ __nv_bfloat16 g_h1h[MM*EE],  g_h1l[MM*EE];
__device__ __nv_bfloat16 g_h2h[MM*EE],  g_h2l[MM*EE];
__device__ __nv_bfloat16 g_th [MM*DHH], g_tl [MM*DHH];
__device__ __nv_bfloat16 g_aoh[MM*HD],  g_aol[MM*HD];
__device__ __nv_bfloat16 g_qhi[MM*HD],  g_qlo[MM*HD];   // fp16 bits (Q single; lo unused)
__device__ __nv_bfloat16 g_khi[MM*HD],  g_klo[MM*HD];   // fp16 bits (K hi/lo)
__device__ __nv_bfloat16 g_vhi[MM*HD],  g_vlo[MM*HD];   // fp16 bits (V hi/lo)
__device__ __nv_bfloat16 g_wqh[EE*HD],  g_wql[EE*HD];
__device__ __nv_bfloat16 g_wkh[EE*HD],  g_wkl[EE*HD];
__device__ __nv_bfloat16 g_wvh[EE*HD],  g_wvl[EE*HD];
__device__ __nv_bfloat16 g_woh[HD*EE],  g_wol[HD*EE];
__device__ __nv_bfloat16 g_f1h[EE*DHH], g_f1l[EE*DHH];
__device__ __nv_bfloat16 g_f2h[DHH*EE], g_f2l[DHH*EE];

// ======================= warp MMA helpers (baseline PTX) =====================
__device__ __forceinline__ uint32_t smem_u32(const void* p) {
    uint32_t a;
    asm("{ .reg .u64 t; cvta.to.shared.u64 t, %1; cvt.u32.u64 %0, t; }"
        : "=r"(a) : "l"(p));
    return a;
}
__device__ __forceinline__ void mma16816(float* c, const uint32_t* a, const uint32_t* b) {
    asm volatile(
        "mma.sync.aligned.m16n8k16.row.col.f32.bf16.bf16.f32 "
        "{%0,%1,%2,%3}, {%4,%5,%6,%7}, {%8,%9}, {%0,%1,%2,%3};"
        : "+f"(c[0]), "+f"(c[1]), "+f"(c[2]), "+f"(c[3])
        : "r"(a[0]), "r"(a[1]), "r"(a[2]), "r"(a[3]), "r"(b[0]), "r"(b[1]));
}
__device__ __forceinline__ void mma16816h(float* c, const uint32_t* a, const uint32_t* b) {
    asm volatile(
        "mma.sync.aligned.m16n8k16.row.col.f32.f16.f16.f32 "
        "{%0,%1,%2,%3}, {%4,%5,%6,%7}, {%8,%9}, {%0,%1,%2,%3};"
        : "+f"(c[0]), "+f"(c[1]), "+f"(c[2]), "+f"(c[3])
        : "r"(a[0]), "r"(a[1]), "r"(a[2]), "r"(a[3]), "r"(b[0]), "r"(b[1]));
}
__device__ __forceinline__ void ldsm_x4(uint32_t* r, uint32_t addr) {
    asm volatile("ldmatrix.sync.aligned.m8n8.x4.shared.b16 {%0,%1,%2,%3}, [%4];"
        : "=r"(r[0]), "=r"(r[1]), "=r"(r[2]), "=r"(r[3]) : "r"(addr));
}
__device__ __forceinline__ void ldsm_x4_t(uint32_t* r, uint32_t addr) {
    asm volatile("ldmatrix.sync.aligned.m8n8.x4.trans.shared.b16 {%0,%1,%2,%3}, [%4];"
        : "=r"(r[0]), "=r"(r[1]), "=r"(r[2]), "=r"(r[3]) : "r"(addr));
}
__device__ __forceinline__ uint32_t pack_bf2(float a, float b) {
    __nv_bfloat162 h = __halves2bfloat162(__float2bfloat16(a), __float2bfloat16(b));
    return *(uint32_t*)&h;
}
__device__ __forceinline__ uint32_t pack_hf2(float a, float b) {
    __half2 h = __halves2half2(__float2half(a), __float2half(b));
    return *(uint32_t*)&h;
}
__device__ __forceinline__ void cp16(uint32_t smem_addr, const void* gptr) {
    asm volatile("cp.async.cg.shared.global [%0], [%1], 16;"
        :: "r"(smem_addr), "l"(gptr) : "memory");
}
#define CP_COMMIT() asm volatile("cp.async.commit_group;" ::: "memory")
#define CP_WAIT(n)  asm volatile("cp.async.wait_group %0;" :: "n"(n) : "memory")

// 256B-row swizzle (B tiles, FA tiles); 128B-row swizzle (A tiles)
__device__ __forceinline__ uint32_t boff(int r, int cbyte) {
    return (uint32_t)(r * 256 + (cbyte ^ ((r & 7) << 4)));
}
__device__ __forceinline__ uint32_t aoff(int r, int cbyte) {
    return (uint32_t)(r * 128 + (cbyte ^ ((r & 7) << 4)));
}

// ---------------- fp32 -> bf16 hi/lo split: all six weights in ONE launch ----
__global__ void split6(const float* __restrict__ a0, const float* __restrict__ a1,
                       const float* __restrict__ a2, const float* __restrict__ a3,
                       const float* __restrict__ a4, const float* __restrict__ a5,
                       __nv_bfloat16* h0, __nv_bfloat16* l0,
                       __nv_bfloat16* h1, __nv_bfloat16* l1,
                       __nv_bfloat16* h2, __nv_bfloat16* l2,
                       __nv_bfloat16* h3, __nv_bfloat16* l3,
                       __nv_bfloat16* h4, __nv_bfloat16* l4,
                       __nv_bfloat16* h5, __nv_bfloat16* l5) {
    const float* ws[6] = {a0, a1, a2, a3, a4, a5};
    __nv_bfloat16* hs[6] = {h0, h1, h2, h3, h4, h5};
    __nv_bfloat16* ls[6] = {l0, l1, l2, l3, l4, l5};
    int b = blockIdx.x, wi, off;
    if (b < 1024) { wi = b >> 8;       off = (b & 255) * 1024; }
    else          { b -= 1024; wi = 4 + (b >> 6); off = (b & 63) * 1024; }
    int i = off + threadIdx.x * 4;
    float4 v = *(const float4*)(ws[wi] + i);
    __nv_bfloat16 b0 = __float2bfloat16(v.x), b1 = __float2bfloat16(v.y);
    __nv_bfloat16 b2 = __float2bfloat16(v.z), b3 = __float2bfloat16(v.w);
    __nv_bfloat162 hh01 = __halves2bfloat162(b0, b1), hh23 = __halves2bfloat162(b2, b3);
    *(uint2*)(hs[wi] + i) = make_uint2(*(uint32_t*)&hh01, *(uint32_t*)&hh23);
    uint32_t l01 = pack_bf2(v.x - __bfloat162float(b0), v.y - __bfloat162float(b1));
    uint32_t l23 = pack_bf2(v.z - __bfloat162float(b2), v.w - __bfloat162float(b3));
    *(uint2*)(ls[wi] + i) = make_uint2(l01, l23);
}

// ---------------- split-K reduce: out = resid (+bias) + sum partials --------
template<int NS, bool BIAS>
__global__ void reduce_k(const float* __restrict__ part, const float* __restrict__ resid,
                         const float* __restrict__ bias, float* __restrict__ out) {
    int i = (blockIdx.x * 256 + threadIdx.x) * 4;
    float4 acc = *(const float4*)(resid + i);
    if (BIAS) {
        float4 bv = *(const float4*)(bias + (i & (EE - 1)));
        acc.x += bv.x; acc.y += bv.y; acc.z += bv.z; acc.w += bv.w;
    }
    #pragma unroll
    for (int z = 0; z < NS; z++) {
        float4 p = *(const float4*)(part + (size_t)z * (MM * EE) + i);
        acc.x += p.x; acc.y += p.y; acc.z += p.z; acc.w += p.w;
    }
    *(float4*)(out + i) = acc;
}

// ---------------- LayerNorm: one warp per row, bf16 hi/lo out ---------------
__global__ void ln_kernel(const float* __restrict__ x, const float* __restrict__ g,
                          const float* __restrict__ b,
                          __nv_bfloat16* __restrict__ ohi, __nv_bfloat16* __restrict__ olo) {
    int warp = threadIdx.x >> 5, lane = threadIdx.x & 31;
    int row = blockIdx.x * 8 + warp;
    float4 v = ((const float4*)(x + (size_t)row * EE))[lane];
    float s = v.x + v.y + v.z + v.w;
    #pragma unroll
    for (int o = 16; o; o >>= 1) s += __shfl_xor_sync(0xffffffffu, s, o);
    float mu = s * (1.0f / EE);
    float d0 = v.x - mu, d1 = v.y - mu, d2 = v.z - mu, d3 = v.w - mu;
    float q = d0*d0 + d1*d1 + d2*d2 + d3*d3;
    #pragma unroll
    for (int o = 16; o; o >>= 1) q += __shfl_xor_sync(0xffffffffu, q, o);
    float inv = rsqrtf(q * (1.0f / EE) + 1e-5f);
    float4 gg = ((const float4*)g)[lane];
    float4 bb = ((const float4*)b)[lane];
    float r0 = d0 * inv * gg.x + bb.x;
    float r1 = d1 * inv * gg.y + bb.y;
    float r2 = d2 * inv * gg.z + bb.z;
    float r3 = d3 * inv * gg.w + bb.w;
    __nv_bfloat16 h0 = __float2bfloat16(r0), h1 = __float2bfloat16(r1);
    __nv_bfloat16 h2 = __float2bfloat16(r2), h3 = __float2bfloat16(r3);
    __nv_bfloat162 hh01 = __halves2bfloat162(h0, h1), hh23 = __halves2bfloat162(h2, h3);
    size_t base = (size_t)row * EE + lane * 4;
    *(uint2*)(ohi + base) = make_uint2(*(uint32_t*)&hh01, *(uint32_t*)&hh23);
    uint32_t l01 = pack_bf2(r0 - __bfloat162float(h0), r1 - __bfloat162float(h1));
    uint32_t l23 = pack_bf2(r2 - __bfloat162float(h2), r3 - __bfloat162float(h3));
    *(uint2*)(olo + base) = make_uint2(l01, l23);
}

// ---- fused split-K reduce + LayerNorm (O-proj epilogue + LN2 in one pass) --
__global__ void reduce_ln(const float* __restrict__ part, const float* __restrict__ resid,
                          const float* __restrict__ g, const float* __restrict__ b,
                          float* __restrict__ x2out,
                          __nv_bfloat16* __restrict__ ohi, __nv_bfloat16* __restrict__ olo) {
    int warp = threadIdx.x >> 5, lane = threadIdx.x & 31;
    int row = blockIdx.x * 8 + warp;
    size_t i = (size_t)row * EE + lane * 4;
    float4 v = *(const float4*)(resid + i);
    #pragma unroll
    for (int z = 0; z < 4; z++) {
        float4 p = *(const float4*)(part + (size_t)z * (MM * EE) + i);
        v.x += p.x; v.y += p.y; v.z += p.z; v.w += p.w;
    }
    *(float4*)(x2out + i) = v;
    float s = v.x + v.y + v.z + v.w;
    #pragma unroll
    for (int o = 16; o; o >>= 1) s += __shfl_xor_sync(0xffffffffu, s, o);
    float mu = s * (1.0f / EE);
    float d0 = v.x - mu, d1 = v.y - mu, d2 = v.z - mu, d3 = v.w - mu;
    float q = d0*d0 + d1*d1 + d2*d2 + d3*d3;
    #pragma unroll
    for (int o = 16; o; o >>= 1) q += __shfl_xor_sync(0xffffffffu, q, o);
    float inv = rsqrtf(q * (1.0f / EE) + 1e-5f);
    float4 gg = ((const float4*)g)[lane];
    float4 bb = ((const float4*)b)[lane];
    float r0 = d0 * inv * gg.x + bb.x;
    float r1 = d1 * inv * gg.y + bb.y;
    float r2 = d2 * inv * gg.z + bb.z;
    float r3 = d3 * inv * gg.w + bb.w;
    __nv_bfloat16 h0 = __float2bfloat16(r0), h1 = __float2bfloat16(r1);
    __nv_bfloat16 h2 = __float2bfloat16(r2), h3 = __float2bfloat16(r3);
    __nv_bfloat162 hh01 = __halves2bfloat162(h0, h1), hh23 = __halves2bfloat162(h2, h3);
    *(uint2*)(ohi + i) = make_uint2(*(uint32_t*)&hh01, *(uint32_t*)&hh23);
    uint32_t l01 = pack_bf2(r0 - __bfloat162float(h0), r1 - __bfloat162float(h1));
    uint32_t l23 = pack_bf2(r2 - __bfloat162float(h2), r3 - __bfloat162float(h3));
    *(uint2*)(olo + i) = make_uint2(l01, l23);
}

// =============== shared smem layout for projection GEMMs (2 stages) =========
#define MM3_AHI 0u
#define MM3_ALO 16384u
#define MM3_BHI 32768u
#define MM3_BLO 49152u
#define MM3_STAGE 65536u
#define MM3_SMEM 131072

// =============== fused QKV projection (pipelined, bf16x3) ===================
// Outputs: Q single fp16 (hi only), K fp16 hi/lo, V fp16 hi/lo.
__global__ __launch_bounds__(256, 1)
void qkv_mm(float qscale)
{
    extern __shared__ char sm[];
    uint32_t sb = smem_u32(sm);
    const int tid = threadIdx.x;
    const int w = tid >> 5, ln = tid & 31;
    const int tig = ln & 3, gid = ln >> 2;
    const int mi = blockIdx.x >> 4;
    const int n0 = (blockIdx.x & 15) * 128;
    const int m0 = blockIdx.y * 128;
    const __nv_bfloat16* Bh_ = (mi == 0) ? g_wqh : (mi == 1) ? g_wkh : g_wvh;
    const __nv_bfloat16* Bl_ = (mi == 0) ? g_wql : (mi == 1) ? g_wkl : g_wvl;
    __nv_bfloat16* Oh_ = (mi == 0) ? g_qhi : (mi == 1) ? g_khi : g_vhi;
    __nv_bfloat16* Ol_ = (mi == 0) ? g_qlo : (mi == 1) ? g_klo : g_vlo;
    const float scale = (mi == 0) ? qscale : 1.0f;

    float C[16][4];
    #pragma unroll
    for (int j = 0; j < 16; j++)
        #pragma unroll
        for (int e = 0; e < 4; e++) C[j][e] = 0.f;

    const int arow = 16 * w + ((ln >> 3) & 1) * 8 + (ln & 7);
    const int akb  = (ln >> 4) * 16;
    const int brow = ((ln >> 3) & 1) * 8 + (ln & 7);
    const int bcb  = (ln >> 4) << 4;

    // prologue: prefetch k-iter 0 into stage 0
    for (int f = tid; f < 1024; f += 256) {
        int r = f >> 3, seg = f & 7;
        size_t g = (size_t)(m0 + r) * EE + seg * 8;
        uint32_t so = aoff(r, seg * 16);
        cp16(sb + MM3_AHI + so, g_h1h + g);
        cp16(sb + MM3_ALO + so, g_h1l + g);
    }
    for (int f = tid; f < 1024; f += 256) {
        int r = f >> 4, seg = f & 15;
        size_t g = (size_t)r * HD + n0 + seg * 8;
        uint32_t so = boff(r, seg * 16);
        cp16(sb + MM3_BHI + so, Bh_ + g);
        cp16(sb + MM3_BLO + so, Bl_ + g);
    }
    CP_COMMIT();

    #pragma unroll
    for (int it = 0; it < 2; it++) {
        uint32_t st = (uint32_t)(it & 1) * MM3_STAGE;
        __syncthreads();
        if (it == 0) {
            for (int f = tid; f < 1024; f += 256) {
                int r = f >> 3, seg = f & 7;
                size_t g = (size_t)(m0 + r) * EE + 64 + seg * 8;
                uint32_t so = aoff(r, seg * 16);
                cp16(sb + MM3_STAGE + MM3_AHI + so, g_h1h + g);
                cp16(sb + MM3_STAGE + MM3_ALO + so, g_h1l + g);
            }
            for (int f = tid; f < 1024; f += 256) {
                int r = f >> 4, seg = f & 15;
                size_t g = (size_t)(64 + r) * HD + n0 + seg * 8;
                uint32_t so = boff(r, seg * 16);
                cp16(sb + MM3_STAGE + MM3_BHI + so, Bh_ + g);
                cp16(sb + MM3_STAGE + MM3_BLO + so, Bl_ + g);
            }
            CP_COMMIT();
            CP_WAIT(1);
        } else {
            CP_WAIT(0);
        }
        __syncthreads();

        uint32_t Ah[4][4], Al[4][4];
        #pragma unroll
        for (int kk = 0; kk < 4; kk++) {
            uint32_t off = aoff(arow, kk * 32 + akb);
            ldsm_x4(Ah[kk], sb + st + MM3_AHI + off);
            ldsm_x4(Al[kk], sb + st + MM3_ALO + off);
        }
        #pragma unroll
        for (int jp = 0; jp < 8; jp++) {
            int ncb = 32 * jp;
            #pragma unroll
            for (int kk = 0; kk < 4; kk++) {
                uint32_t off = boff(16 * kk + brow, ncb + bcb);
                uint32_t Bh[4], Bl[4];
                ldsm_x4_t(Bh, sb + st + MM3_BHI + off);
                mma16816(C[2*jp],   Ah[kk], Bh);
                mma16816(C[2*jp+1], Ah[kk], Bh + 2);
                mma16816(C[2*jp],   Al[kk], Bh);
                mma16816(C[2*jp+1], Al[kk], Bh + 2);
                ldsm_x4_t(Bl, sb + st + MM3_BLO + off);
                mma16816(C[2*jp],   Ah[kk], Bl);
                mma16816(C[2*jp+1], Ah[kk], Bl + 2);
            }
        }
    }

    // epilogue: scale, RoPE (Q/K), fp16 pack to (B,H,S,D)
    const int r0 = m0 + 16 * w + gid;
    const int r1 = r0 + 8;
    int b_ = r0 >> 11, s0 = r0 & 2047, s1 = r1 & 2047;
    #pragma unroll
    for (int j = 0; j < 16; j++) {
        int colg = n0 + 8 * j + 2 * tig;
        int h = colg >> 7, d = colg & 127;
        float o00 = C[j][0] * scale, o01 = C[j][1] * scale;
        float o10 = C[j][2] * scale, o11 = C[j][3] * scale;
        if (mi < 2) {
            int t2 = d >> 1;
            float f = expf((float)t2 * -0.14391157f);
            float si0, co0, si1, co1;
            sincosf((float)s0 * f, &si0, &co0);
            sincosf((float)s1 * f, &si1, &co1);
            float a = o00 * co0 - o01 * si0, b2 = o00 * si0 + o01 * co0;
            o00 = a; o01 = b2;
            a = o10 * co1 - o11 * si1; b2 = o10 * si1 + o11 * co1;
            o10 = a; o11 = b2;
        }
        size_t oi0 = (((size_t)(b_ * HH + h) * SS + s0) * DD + d);
        size_t oi1 = (((size_t)(b_ * HH + h) * SS + s1) * DD + d);
        __half h00 = __float2half(o00), h01 = __float2half(o01);
        __half h10 = __float2half(o10), h11 = __float2half(o11);
        __half2 p0 = __halves2half2(h00, h01);
        __half2 p1 = __halves2half2(h10, h11);
        *(uint32_t*)(Oh_ + oi0) = *(uint32_t*)&p0;
        *(uint32_t*)(Oh_ + oi1) = *(uint32_t*)&p1;
        if (mi >= 1) {   // K and V keep a lo term; Q is single fp16
            *(uint32_t*)(Ol_ + oi0) = pack_hf2(o00 - __half2float(h00), o01 - __half2float(h01));
            *(uint32_t*)(Ol_ + oi1) = pack_hf2(o10 - __half2float(h10), o11 - __half2float(h11));
        }
    }
}

// =============== bf16x3 tensor-core GEMM (pipelined) ========================
// MODE 4: gelu(acc + bias) -> bf16 hi/lo               (fc1)
// MODE 6: split-K partial: fp32 to out + blockIdx.x*M*N, k in [bx*kspl, +kspl)
template<int MODE, bool AG, bool HALFM>
__global__ __launch_bounds__(256)
void mm3(const __nv_bfloat16* __restrict__ Ahi, const __nv_bfloat16* __restrict__ Alo,
         const __nv_bfloat16* __restrict__ Bhi, const __nv_bfloat16* __restrict__ Blo,
         const float* __restrict__ bias, const float* __restrict__ resid,
         float* __restrict__ out,
         __nv_bfloat16* __restrict__ ohi, __nv_bfloat16* __restrict__ olo,
         int M, int N, int K, int kspl, float qscale)
{
    extern __shared__ char sm[];
    uint32_t sb = smem_u32(sm);
    constexpr int MT = HALFM ? 64 : 128;
    constexpr int NJ = HALFM ? 8 : 16;
    const int tid = threadIdx.x;
    const int w = tid >> 5, ln = tid & 31;
    const int tig = ln & 3, gid = ln >> 2;
    const int wr = HALFM ? (w & 3) : w;
    const int wc = HALFM ? (w >> 2) * 64 : 0;
    const int m0 = blockIdx.y * MT;
    const int n0 = (MODE == 6) ? 0 : blockIdx.x * 128;
    const int kb = (MODE == 6) ? blockIdx.x * kspl : 0;
    const int ke = (MODE == 6) ? kb + kspl : K;
    const int niter = (ke - kb) >> 6;

    float C[NJ][4];
    #pragma unroll
    for (int j = 0; j < NJ; j++)
        #pragma unroll
        for (int e = 0; e < 4; e++) C[j][e] = 0.f;

    const int arow = 16 * wr + ((ln >> 3) & 1) * 8 + (ln & 7);
    const int akb  = (ln >> 4) * 16;
    const int brow = ((ln >> 3) & 1) * 8 + (ln & 7);
    const int bcb  = (ln >> 4) << 4;

    // prologue: prefetch iter 0
    {
        int k0 = kb;
        for (int f = tid; f < MT * 8; f += 256) {
            int r = f >> 3, seg = f & 7;
            size_t g;
            if (!AG) {
                g = (size_t)(m0 + r) * K + k0 + seg * 8;
            } else {
                int rr = m0 + r;
                int b_ = rr >> 11, s_ = rr & 2047;
                int kk = k0 + seg * 8;
                g = ((size_t)(b_ * HH + (kk >> 7)) * SS + s_) * DD + (kk & 127);
            }
            uint32_t so = aoff(r, seg * 16);
            cp16(sb + MM3_AHI + so, Ahi + g);
            cp16(sb + MM3_ALO + so, Alo + g);
        }
        for (int f = tid; f < 1024; f += 256) {
            int r = f >> 4, seg = f & 15;
            size_t g = (size_t)(k0 + r) * N + n0 + seg * 8;
            uint32_t so = boff(r, seg * 16);
            cp16(sb + MM3_BHI + so, Bhi + g);
            cp16(sb + MM3_BLO + so, Blo + g);
        }
        CP_COMMIT();
    }

    for (int it = 0; it < niter; it++) {
        uint32_t st = (uint32_t)(it & 1) * MM3_STAGE;
        __syncthreads();
        if (it + 1 < niter) {
            int k0 = kb + (it + 1) * 64;
            uint32_t stn = (uint32_t)((it + 1) & 1) * MM3_STAGE;
            for (int f = tid; f < MT * 8; f += 256) {
                int r = f >> 3, seg = f & 7;
                size_t g;
                if (!AG) {
                    g = (size_t)(m0 + r) * K + k0 + seg * 8;
                } else {
                    int rr = m0 + r;
                    int b_ = rr >> 11, s_ = rr & 2047;
                    int kk = k0 + seg * 8;
                    g = ((size_t)(b_ * HH + (kk >> 7)) * SS + s_) * DD + (kk & 127);
                }
                uint32_t so = aoff(r, seg * 16);
                cp16(sb + stn + MM3_AHI + so, Ahi + g);
                cp16(sb + stn + MM3_ALO + so, Alo + g);
            }
            for (int f = tid; f < 1024; f += 256) {
                int r = f >> 4, seg = f & 15;
                size_t g = (size_t)(k0 + r) * N + n0 + seg * 8;
                uint32_t so = boff(r, seg * 16);
                cp16(sb + stn + MM3_BHI + so, Bhi + g);
                cp16(sb + stn + MM3_BLO + so, Blo + g);
            }
            CP_COMMIT();
            CP_WAIT(1);
        } else {
            CP_WAIT(0);
        }
        __syncthreads();

        uint32_t Ah[4][4], Al[4][4];
        #pragma unroll
        for (int kk = 0; kk < 4; kk++) {
            uint32_t off = aoff(arow, kk * 32 + akb);
            ldsm_x4(Ah[kk], sb + st + MM3_AHI + off);
            ldsm_x4(Al[kk], sb + st + MM3_ALO + off);
        }
        #pragma unroll
        for (int jp = 0; jp < NJ / 2; jp++) {
            int ncb = (wc + 16 * jp) * 2;
            #pragma unroll
            for (int kk = 0; kk < 4; kk++) {
                uint32_t off = boff(16 * kk + brow, ncb + bcb);
                uint32_t Bh[4], Bl[4];
                ldsm_x4_t(Bh, sb + st + MM3_BHI + off);
                mma16816(C[2*jp],   Ah[kk], Bh);
                mma16816(C[2*jp+1], Ah[kk], Bh + 2);
                mma16816(C[2*jp],   Al[kk], Bh);
                mma16816(C[2*jp+1], Al[kk], Bh + 2);
                ldsm_x4_t(Bl, sb + st + MM3_BLO + off);
                mma16816(C[2*jp],   Ah[kk], Bl);
                mma16816(C[2*jp+1], Ah[kk], Bl + 2);
            }
        }
    }

    const int r0 = m0 + 16 * wr + gid;
    const int r1 = r0 + 8;
    if (MODE == 6) {
        float* po = out + (size_t)blockIdx.x * M * N;
        #pragma unroll
        for (int j = 0; j < NJ; j++) {
            int colg = wc + 8 * j + 2 * tig;
            size_t i0 = (size_t)r0 * N + colg;
            size_t i1 = (size_t)r1 * N + colg;
            *(float2*)(po + i0) = make_float2(C[j][0], C[j][1]);
            *(float2*)(po + i1) = make_float2(C[j][2], C[j][3]);
        }
    } else if (MODE == 4) {
        #pragma unroll
        for (int j = 0; j < NJ; j++) {
            int colg = n0 + wc + 8 * j + 2 * tig;
            size_t i0 = (size_t)r0 * N + colg;
            size_t i1 = (size_t)r1 * N + colg;
            float v00 = C[j][0], v01 = C[j][1], v10 = C[j][2], v11 = C[j][3];
            float b0 = bias[colg], b1 = bias[colg + 1];
            v00 += b0; v01 += b1; v10 += b0; v11 += b1;
            v00 = 0.5f * v00 * (1.0f + erff(v00 * 0.70710678f));
            v01 = 0.5f * v01 * (1.0f + erff(v01 * 0.70710678f));
            v10 = 0.5f * v10 * (1.0f + erff(v10 * 0.70710678f));
            v11 = 0.5f * v11 * (1.0f + erff(v11 * 0.70710678f));
            __nv_bfloat16 h00 = __float2bfloat16(v00), h01 = __float2bfloat16(v01);
            __nv_bfloat16 h10 = __float2bfloat16(v10), h11 = __float2bfloat16(v11);
            __nv_bfloat162 p0 = __halves2bfloat162(h00, h01);
            __nv_bfloat162 p1 = __halves2bfloat162(h10, h11);
            *(uint32_t*)(ohi + i0) = *(uint32_t*)&p0;
            *(uint32_t*)(ohi + i1) = *(uint32_t*)&p1;
            *(uint32_t*)(olo + i0) = pack_bf2(v00 - __bfloat162float(h00), v01 - __bfloat162float(h01));
            *(uint32_t*)(olo + i1) = pack_bf2(v10 - __bfloat162float(h10), v11 - __bfloat162float(h11));
        }
    }
}

// ====== mma.sync flash attention (fp16x2 S, fp16x2 PV, 2 CTAs/SM) ===========
// CTA: 128 threads, 64 query rows. Grid 1024 (globally-descending work).
// Smem/CTA = 96KB: K hi/lo [0,32K), V hi/lo double-buffer [32K,96K).
// Q single fp16 (2^-11); K,V fp16 hi/lo (exact to 2^-22); 2-term S and PV.
#define FA_KHI 0u
#define FA_KLO 16384u
#define FA_V0  32768u
#define FA_VST 32768u
#define FA_SMEM 98304

__device__ __forceinline__ uint32_t fa_off(int r, int cbyte) {
    return (uint32_t)(r * 256 + (cbyte ^ ((r & 7) << 4)));
}

__global__ __launch_bounds__(128, 2)
void fa_mma(const __nv_bfloat16* __restrict__ qhi, const __nv_bfloat16* __restrict__ qlo,
            const __nv_bfloat16* __restrict__ khi, const __nv_bfloat16* __restrict__ klo,
            const __nv_bfloat16* __restrict__ vhi, const __nv_bfloat16* __restrict__ vlo,
            __nv_bfloat16* __restrict__ Ohi, __nv_bfloat16* __restrict__ Olo)
{
    extern __shared__ char sm[];
    uint32_t sb = smem_u32(sm);
    const int tid = threadIdx.x;
    const int w = tid >> 5, ln = tid & 31;
    const int tig = ln & 3, gid = ln >> 2;
    const int bid = blockIdx.x;
    const int m0 = (31 - (bid >> 5)) * 64;    // globally descending work
    const int bh = bid & 31;
    const size_t base = (size_t)bh * SS * DD;

    // ---- stage Q (single fp16) via K region (transient) ----
    for (int f = tid; f < 1024; f += 128) {
        int r = f >> 4, c16 = f & 15;
        size_t g = base + (size_t)(m0 + r) * DD + c16 * 8;
        uint32_t so = fa_off(r, c16 * 16);
        *(uint4*)(sm + FA_KHI + so) = *(const uint4*)(qhi + g);
    }
    __syncthreads();
    const int qrow = 16 * w + ((ln >> 3) & 1) * 8 + (ln & 7);
    const int qkb  = (ln >> 4) * 16;
    uint32_t Qh[8][4];
    #pragma unroll
    for (int kk = 0; kk < 8; kk++)
        ldsm_x4(Qh[kk], sb + FA_KHI + fa_off(qrow, kk * 32 + qkb));
    __syncthreads();

    float Oa[16][4];
    #pragma unroll
    for (int j = 0; j < 16; j++)
        #pragma unroll
        for (int e = 0; e < 4; e++) Oa[j][e] = 0.f;
    float m0r = -1e30f, m1r = -1e30f, l0r = 0.f, l1r = 0.f;

    const int grow0 = m0 + 16 * w + gid;
    const int grow1 = grow0 + 8;
    const int nk = m0 / 64 + 1;

    // ---- prologue: K(0), V(0) ----
    for (int f = tid; f < 1024; f += 128) {
        int r = f >> 4, c16 = f & 15;
        size_t g = base + (size_t)r * DD + c16 * 8;
        uint32_t so = fa_off(r, c16 * 16);
        cp16(sb + FA_KHI + so, khi + g);
        cp16(sb + FA_KLO + so, klo + g);
        cp16(sb + FA_V0 + so, vhi + g);
        cp16(sb + FA_V0 + 16384 + so, vlo + g);
    }
    CP_COMMIT();

    for (int t = 0; t < nk; t++) {
        int n0 = t * 64;
        uint32_t vb = FA_V0 + (uint32_t)(t & 1) * FA_VST;
        CP_WAIT(0);        // K(t), V(t) resident
        __syncthreads();

        // ---- S = Q K^T (2-term fp16: Q*Kh + Q*Kl) ----
        float S[8][4];
        #pragma unroll
        for (int j = 0; j < 8; j++)
            #pragma unroll
            for (int e = 0; e < 4; e++) S[j][e] = 0.f;
        {
            int brow = ((ln >> 4) << 3) + (ln & 7);
            int bkb  = ((ln >> 3) & 1) << 4;
            #pragma unroll
            for (int kk = 0; kk < 8; kk++) {
                #pragma unroll
                for (int jp = 0; jp < 4; jp++) {
                    int r_ = 16 * jp + brow;
                    uint32_t off = fa_off(r_, kk * 32 + bkb);
                    uint32_t Bh[4], Bl[4];
                    ldsm_x4(Bh, sb + FA_KHI + off);
                    mma16816h(S[2*jp],   Qh[kk], Bh);
                    mma16816h(S[2*jp+1], Qh[kk], Bh + 2);
                    ldsm_x4(Bl, sb + FA_KLO + off);
                    mma16816h(S[2*jp],   Qh[kk], Bl);
                    mma16816h(S[2*jp+1], Qh[kk], Bl + 2);
                }
            }
        }
        __syncthreads();   // all warps done reading K(t)

        // ---- prefetch K(t+1) and V(t+1) (overlaps softmax + PV below) ----
        if (t + 1 < nk) {
            int n1 = n0 + 64;
            uint32_t vbn = FA_V0 + (uint32_t)((t + 1) & 1) * FA_VST;
            for (int f = tid; f < 1024; f += 128) {
                int r = f >> 4, c16 = f & 15;
                size_t g = base + (size_t)(n1 + r) * DD + c16 * 8;
                uint32_t so = fa_off(r, c16 * 16);
                cp16(sb + FA_KHI + so, khi + g);
                cp16(sb + FA_KLO + so, klo + g);
                cp16(sb + vbn + so, vhi + g);
                cp16(sb + vbn + 16384 + so, vlo + g);
            }
            CP_COMMIT();
        }

        // ---- causal mask (diagonal tile only) ----
        if (n0 + 63 > m0 + 16 * w) {
            #pragma unroll
            for (int j = 0; j < 8; j++) {
                int c = n0 + 8 * j + 2 * tig;
                if (c     > grow0) S[j][0] = -1e30f;
                if (c + 1 > grow0) S[j][1] = -1e30f;
                if (c     > grow1) S[j][2] = -1e30f;
                if (c + 1 > grow1) S[j][3] = -1e30f;
            }
        }

        // ---- online softmax (P packed as single fp16) ----
        float mx0 = -1e30f, mx1 = -1e30f;
        #pragma unroll
        for (int j = 0; j < 8; j++) {
            mx0 = fmaxf(mx0, fmaxf(S[j][0], S[j][1]));
            mx1 = fmaxf(mx1, fmaxf(S[j][2], S[j][3]));
        }
        mx0 = fmaxf(mx0, __shfl_xor_sync(0xffffffffu, mx0, 1));
        mx0 = fmaxf(mx0, __shfl_xor_sync(0xffffffffu, mx0, 2));
        mx1 = fmaxf(mx1, __shfl_xor_sync(0xffffffffu, mx1, 1));
        mx1 = fmaxf(mx1, __shfl_xor_sync(0xffffffffu, mx1, 2));
        float mn0 = fmaxf(m0r, mx0), mn1 = fmaxf(m1r, mx1);
        bool nochg = (mn0 == m0r) && (mn1 == m1r);
        float a0 = nochg ? 1.f : __expf(m0r - mn0);
        float a1 = nochg ? 1.f : __expf(m1r - mn1);
        m0r = mn0; m1r = mn1;
        l0r *= a0; l1r *= a1;

        uint32_t Ph[4][4];
        float ls0 = 0.f, ls1 = 0.f;
        #pragma unroll
        for (int j = 0; j < 8; j++) {
            float p0 = __expf(S[j][0] - mn0);
            float p1 = __expf(S[j][1] - mn0);
            float p2 = __expf(S[j][2] - mn1);
            float p3 = __expf(S[j][3] - mn1);
            ls0 += p0 + p1; ls1 += p2 + p3;
            int kk = j >> 1, q = (j & 1) * 2;
            Ph[kk][q]     = pack_hf2(p0, p1);
            Ph[kk][q + 1] = pack_hf2(p2, p3);
        }
        l0r += ls0; l1r += ls1;

        if (!__all_sync(0xffffffffu, nochg)) {
            #pragma unroll
            for (int j = 0; j < 16; j++) {
                Oa[j][0] *= a0; Oa[j][1] *= a0;
                Oa[j][2] *= a1; Oa[j][3] *= a1;
            }
        }

        // ---- O += P V (2-term fp16: Ph*Vh + Ph*Vl) ----
        {
            int vrow = ((ln >> 3) & 1) * 8 + (ln & 7);
            int vcb  = (ln >> 4) << 4;
            #pragma unroll
            for (int jp = 0; jp < 8; jp++) {
                #pragma unroll
                for (int kk = 0; kk < 4; kk++) {
                    int r_ = 16 * kk + vrow;
                    uint32_t off = fa_off(r_, 32 * jp + vcb);
                    uint32_t Bh[4], Bl[4];
                    ldsm_x4_t(Bh, sb + vb + off);
                    mma16816h(Oa[2*jp],   Ph[kk], Bh);
                    mma16816h(Oa[2*jp+1], Ph[kk], Bh + 2);
                    ldsm_x4_t(Bl, sb + vb + 16384 + off);
                    mma16816h(Oa[2*jp],   Ph[kk], Bl);
                    mma16816h(Oa[2*jp+1], Ph[kk], Bl + 2);
                }
            }
        }
    }

    // ---- finalize: reduce l, normalize, split hi/lo, store ----
    l0r += __shfl_xor_sync(0xffffffffu, l0r, 1);
    l0r += __shfl_xor_sync(0xffffffffu, l0r, 2);
    l1r += __shfl_xor_sync(0xffffffffu, l1r, 1);
    l1r += __shfl_xor_sync(0xffffffffu, l1r, 2);
    float inv0 = 1.0f / l0r, inv1 = 1.0f / l1r;
    #pragma unroll
    for (int j = 0; j < 16; j++) {
        int col = 8 * j + 2 * tig;
        size_t i0 = base + (size_t)grow0 * DD + col;
        size_t i1 = base + (size_t)grow1 * DD + col;
        float v00 = Oa[j][0] * inv0, v01 = Oa[j][1] * inv0;
        float v10 = Oa[j][2] * inv1, v11 = Oa[j][3] * inv1;
        __nv_bfloat16 h00 = __float2bfloat16(v00), h01 = __float2bfloat16(v01);
        __nv_bfloat16 h10 = __float2bfloat16(v10), h11 = __float2bfloat16(v11);
        __nv_bfloat162 p0 = __halves2bfloat162(h00, h01);
        __nv_bfloat162 p1 = __halves2bfloat162(h10, h11);
        *(uint32_t*)(Ohi + i0) = *(uint32_t*)&p0;
        *(uint32_t*)(Ohi + i1) = *(uint32_t*)&p1;
        *(uint32_t*)(Olo + i0) = pack_bf2(v00 - __bfloat162float(h00), v01 - __bfloat162float(h01));
        *(uint32_t*)(Olo + i1) = pack_bf2(v10 - __bfloat162float(h10), v11 - __bfloat162float(h11));
    }
}

// ---------------- launch -----------------------------------------------------
extern "C" void kernel_launch(void* const* d_in, const int* in_sizes, int n_in,
                              void* d_out, int out_size) {
    const float* x        = (const float*)d_in[0];
    const float* W_q      = (const float*)d_in[1];
    const float* W_k      = (const float*)d_in[2];
    const float* W_v      = (const float*)d_in[3];
    const float* W_o      = (const float*)d_in[4];
    const float* ln_attn_g= (const float*)d_in[5];
    const float* ln_attn_b= (const float*)d_in[6];
    const float* fc1_w    = (const float*)d_in[7];
    const float* fc1_b    = (const float*)d_in[8];
    const float* fc2_w    = (const float*)d_in[9];
    const float* fc2_b    = (const float*)d_in[10];
    const float* ln_mlp_g = (const float*)d_in[11];
    const float* ln_mlp_b = (const float*)d_in[12];
    float* out = (float*)d_out;

    float *x2, *part;
    __nv_bfloat16 *h1h, *h1l, *h2h, *h2l, *th, *tl, *aoh, *aol;
    __nv_bfloat16 *qhi, *qlo, *khi, *klo, *vhi, *vlo;
    __nv_bfloat16 *wqh, *wql, *wkh, *wkl, *wvh, *wvl, *woh, *wol, *f1h, *f1l, *f2h, *f2l;
    cudaGetSymbolAddress((void**)&x2,  g_x2);
    cudaGetSymbolAddress((void**)&part, g_part);
    cudaGetSymbolAddress((void**)&h1h, g_h1h); cudaGetSymbolAddress((void**)&h1l, g_h1l);
    cudaGetSymbolAddress((void**)&h2h, g_h2h); cudaGetSymbolAddress((void**)&h2l, g_h2l);
    cudaGetSymbolAddress((void**)&th,  g_th);  cudaGetSymbolAddress((void**)&tl,  g_tl);
    cudaGetSymbolAddress((void**)&aoh, g_aoh); cudaGetSymbolAddress((void**)&aol, g_aol);
    cudaGetSymbolAddress((void**)&qhi, g_qhi); cudaGetSymbolAddress((void**)&qlo, g_qlo);
    cudaGetSymbolAddress((void**)&khi, g_khi); cudaGetSymbolAddress((void**)&klo, g_klo);
    cudaGetSymbolAddress((void**)&vhi, g_vhi); cudaGetSymbolAddress((void**)&vlo, g_vlo);
    cudaGetSymbolAddress((void**)&wqh, g_wqh); cudaGetSymbolAddress((void**)&wql, g_wql);
    cudaGetSymbolAddress((void**)&wkh, g_wkh); cudaGetSymbolAddress((void**)&wkl, g_wkl);
    cudaGetSymbolAddress((void**)&wvh, g_wvh); cudaGetSymbolAddress((void**)&wvl, g_wvl);
    cudaGetSymbolAddress((void**)&woh, g_woh); cudaGetSymbolAddress((void**)&wol, g_wol);
    cudaGetSymbolAddress((void**)&f1h, g_f1h); cudaGetSymbolAddress((void**)&f1l, g_f1l);
    cudaGetSymbolAddress((void**)&f2h, g_f2h); cudaGetSymbolAddress((void**)&f2l, g_f2l);

    // 0) split all six weights to bf16 hi/lo in one launch
    split6<<<1152, 256>>>(W_q, W_k, W_v, W_o, fc1_w, fc2_w,
                          wqh, wql, wkh, wkl, wvh, wvl,
                          woh, wol, f1h, f1l, f2h, f2l);

    // 1) LN -> bf16 hi/lo
    ln_kernel<<<MM/8, 256>>>(x, ln_attn_g, ln_attn_b, h1h, h1l);

    // 2) fused QKV projection (Q single fp16; K,V fp16 hi/lo)
    const float qscale = 0.08838834764831845f;  // 1/sqrt(128)
    cudaFuncSetAttribute(qkv_mm, cudaFuncAttributeMaxDynamicSharedMemorySize, MM3_SMEM);
    qkv_mm<<<dim3(48, MM/128), 256, MM3_SMEM>>>(qscale);

    // 3) causal flash attention (fp16x2 S, fp16x2 PV, 2 CTAs/SM)
    cudaFuncSetAttribute(fa_mma, cudaFuncAttributeMaxDynamicSharedMemorySize, FA_SMEM);
    fa_mma<<<1024, 128, FA_SMEM>>>(qhi, qlo, khi, klo, vhi, vlo, aoh, aol);

    // 4) O-projection split-K (4 x 512, pipelined) -> FUSED reduce+residual+LN
    cudaFuncSetAttribute(mm3<6,true,true>,  cudaFuncAttributeMaxDynamicSharedMemorySize, MM3_SMEM);
    cudaFuncSetAttribute(mm3<6,false,true>, cudaFuncAttributeMaxDynamicSharedMemorySize, MM3_SMEM);
    cudaFuncSetAttribute(mm3<4,false,true>, cudaFuncAttributeMaxDynamicSharedMemorySize, MM3_SMEM);
    mm3<6,true,true><<<dim3(4, MM/64), 256, MM3_SMEM>>>(aoh, aol, woh, wol, nullptr, nullptr, part, nullptr, nullptr, MM, EE, HD, 512, 1.0f);
    reduce_ln<<<MM/8, 256>>>(part, x, ln_mlp_g, ln_mlp_b, x2, h2h, h2l);

    // 5) MLP: fc1 (pipelined, HALFM, fused bias+GELU+split), fc2 split-K 4x128
    mm3<4,false,true><<<dim3(DHH/128, MM/64), 256, MM3_SMEM>>>(h2h, h2l, f1h, f1l, fc1_b, nullptr, nullptr, th, tl, MM, DHH, EE, EE, 1.0f);
    mm3<6,false,true><<<dim3(4, MM/64), 256, MM3_SMEM>>>(th, tl, f2h, f2l, nullptr, nullptr, part, nullptr, nullptr, MM, EE, DHH, 128, 1.0f);
    reduce_k<4,true><<<(MM*EE)/1024, 256>>>(part, x2, fc2_b, out);
}